// round 7
// baseline (speedup 1.0000x reference)
#include <cuda_runtime.h>

#define NROWS 204800
#define BN_EPS 1e-5f

#define FD0 100000
#define FD1 1000
#define FD2 100
#define FD3 50
#define PV (FD0 + FD1 + FD2 + FD3)
#define GOFF1 FD0
#define GOFF2 (FD0 + FD1)
#define GOFF3 (FD0 + FD1 + FD2)

#define K1_BLOCKS 800
#define K3_GRID 444
#define K5_GRID 444
#define SETUP_BLOCKS 512
#define TILE_R 128
#define N_TILES (NROWS / TILE_R)   // 1600

typedef unsigned long long u64;

// packed fp32x2 fused multiply-add: one instr, two MACs (FFMA2)
__device__ __forceinline__ u64 fma2(u64 a, u64 b, u64 c) {
    u64 d;
    asm("fma.rn.f32x2 %0, %1, %2, %3;" : "=l"(d) : "l"(a), "l"(b), "l"(c));
    return d;
}
__device__ __forceinline__ float f32x2_sum(u64 v) {
    float lo = __uint_as_float((unsigned)v);
    float hi = __uint_as_float((unsigned)(v >> 32));
    return lo + hi;
}

// Scratch (device globals; no runtime allocation allowed)
__device__ float4 g_G[(size_t)PV * 32];           // fused gather table (P_lo,P_hi,lin,emb)
__device__ float g_A[64 * 8];                     // cont_w folded into w1
__device__ float g_cb[64];                        // b1 + cont_b folded into w1
__device__ float g_h1[(size_t)NROWS * 64];        // pre-BN layer-1 activations
__device__ float g_h2[(size_t)NROWS * 32];        // pre-BN layer-2 activations
__device__ float g_part1[K1_BLOCKS * 128];        // per-block BN1 partials
__device__ float g_part2[K3_GRID * 64];           // per-block BN2 partials
__device__ float g_bn1[128];                      // scale[64], shift[64]
__device__ float g_bn2[64];                       // scale[32], shift[32]
__device__ unsigned g_cnt1 = 0;
__device__ unsigned g_cnt2 = 0;

// ---------------------------------------------------------------------------
// kSetup: cont-fold init AND the fused gather table for all 4 fields.
// g_G[(gOff+v)*32 + lane] = (P[v][lane], P[v][lane+32], lin[v][lane], emb[v][lane])
// where P[v][j] = sum_d emb[v,d] * w1[j, colOff+d].
// ---------------------------------------------------------------------------
__global__ void __launch_bounds__(256) kSetup(
    const float* __restrict__ emb0, const float* __restrict__ emb1,
    const float* __restrict__ emb2, const float* __restrict__ emb3,
    const float* __restrict__ lin0, const float* __restrict__ lin1,
    const float* __restrict__ lin2, const float* __restrict__ lin3,
    const float* __restrict__ w1, const float* __restrict__ b1,
    const float* __restrict__ cont_w, const float* __restrict__ cont_b) {
    int bid = blockIdx.x;
    int lane = threadIdx.x & 31;
    int warp = threadIdx.x >> 5;

    if (bid == 511) {  // cont-feature fold into w1
        int j = threadIdx.x;
        if (j < 64) {
            float cb = b1[j];
            for (int c = 0; c < 8; c++) {
                float a = 0.f;
#pragma unroll
                for (int d = 0; d < 32; d++) {
                    float w = w1[j * 384 + (4 + c) * 32 + d];
                    a = fmaf(cont_w[c * 32 + d], w, a);
                    cb = fmaf(cont_b[c * 32 + d], w, cb);
                }
                g_A[j * 8 + c] = a;
            }
            g_cb[j] = cb;
        }
        return;
    }

    const float* emb;
    const float* lin;
    int V, gOff, colOff, wfirst, nwarp;
    if (bid < 506) {
        emb = emb0; lin = lin0; V = FD0; gOff = 0; colOff = 0;
        wfirst = bid * 8 + warp; nwarp = 506 * 8;
    } else if (bid < 510) {
        emb = emb1; lin = lin1; V = FD1; gOff = GOFF1; colOff = 32;
        wfirst = (bid - 506) * 8 + warp; nwarp = 32;
    } else if (warp < 4) {
        emb = emb2; lin = lin2; V = FD2; gOff = GOFF2; colOff = 64;
        wfirst = warp; nwarp = 4;
    } else {
        emb = emb3; lin = lin3; V = FD3; gOff = GOFF3; colOff = 96;
        wfirst = warp - 4; nwarp = 4;
    }

    float wa[32], wb[32];
#pragma unroll
    for (int d = 0; d < 32; d++) {
        wa[d] = w1[lane * 384 + colOff + d];
        wb[d] = w1[(lane + 32) * 384 + colOff + d];
    }
    for (int v = wfirst; v < V; v += nwarp) {
        float ev = emb[v * 32 + lane];
        float lv = lin[v * 32 + lane];
        float a0 = 0.f, a1 = 0.f;
#pragma unroll
        for (int d = 0; d < 32; d++) {
            float e = __shfl_sync(0xffffffffu, ev, d);
            a0 = fmaf(e, wa[d], a0);
            a1 = fmaf(e, wb[d], a1);
        }
        g_G[(size_t)(gOff + v) * 32 + lane] = make_float4(a0, a1, lv, ev);
    }
}

// ---------------------------------------------------------------------------
// Kernel 1: contiguous 32-row chunk per warp, 2 rows per iteration,
// ONE LDG.128 per (feature,row) from the fused table.
// FM interaction + linear -> out; h1 -> g_h1; BN1 partials; last block
// finalizes BN1.
// ---------------------------------------------------------------------------
__global__ void __launch_bounds__(256) k1(
    const float* __restrict__ x,
    const float* __restrict__ cont_w, const float* __restrict__ cont_b,
    const float* __restrict__ clin_w, const float* __restrict__ clin_b,
    const float* __restrict__ fin_bias,
    const float* __restrict__ g1, const float* __restrict__ beta1,
    float* __restrict__ out) {
    int lane = threadIdx.x & 31;
    int warp = threadIdx.x >> 5;
    int gw = blockIdx.x * 8 + warp;          // 6400 warps x 32 rows = NROWS
    int rbase = gw * 32;

    float cw[8], cbv[8], clw[8], clb[8], A0[8], A1[8];
#pragma unroll
    for (int c = 0; c < 8; c++) {
        cw[c] = cont_w[c * 32 + lane];
        cbv[c] = cont_b[c * 32 + lane];
        clw[c] = clin_w[c * 32 + lane];
        clb[c] = clin_b[c * 32 + lane];
        A0[c] = g_A[lane * 8 + c];
        A1[c] = g_A[(lane + 32) * 8 + c];
    }
    float finb = fin_bias[lane];
    float cb0 = g_cb[lane], cb1 = g_cb[lane + 32];
    float sum0 = 0.f, sq0 = 0.f, sum1 = 0.f, sq1 = 0.f;

    for (int it = 0; it < 16; it++) {
        int rA = rbase + it * 2;
        int rB = rA + 1;
        float xv = 0.f;
        if (lane < 24) xv = x[rA * 12 + lane];
        int iA0 = (int)__shfl_sync(0xffffffffu, xv, 0);
        int iA1 = (int)__shfl_sync(0xffffffffu, xv, 1);
        int iA2 = (int)__shfl_sync(0xffffffffu, xv, 2);
        int iA3 = (int)__shfl_sync(0xffffffffu, xv, 3);
        int iB0 = (int)__shfl_sync(0xffffffffu, xv, 12);
        int iB1 = (int)__shfl_sync(0xffffffffu, xv, 13);
        int iB2 = (int)__shfl_sync(0xffffffffu, xv, 14);
        int iB3 = (int)__shfl_sync(0xffffffffu, xv, 15);
        float xcA[8], xcB[8];
#pragma unroll
        for (int c = 0; c < 8; c++) {
            xcA[c] = __shfl_sync(0xffffffffu, xv, 4 + c);
            xcB[c] = __shfl_sync(0xffffffffu, xv, 16 + c);
        }

        // 8 independent 16B gathers (one per feature per row)
        float4 gA0 = g_G[(size_t)iA0 * 32 + lane];
        float4 gA1 = g_G[(size_t)(GOFF1 + iA1) * 32 + lane];
        float4 gA2 = g_G[(size_t)(GOFF2 + iA2) * 32 + lane];
        float4 gA3 = g_G[(size_t)(GOFF3 + iA3) * 32 + lane];
        float4 gB0 = g_G[(size_t)iB0 * 32 + lane];
        float4 gB1 = g_G[(size_t)(GOFF1 + iB1) * 32 + lane];
        float4 gB2 = g_G[(size_t)(GOFF2 + iB2) * 32 + lane];
        float4 gB3 = g_G[(size_t)(GOFF3 + iB3) * 32 + lane];

        // row A
        {
            float s = gA0.w + gA1.w + gA2.w + gA3.w;
            float sq = gA0.w * gA0.w + gA1.w * gA1.w + gA2.w * gA2.w + gA3.w * gA3.w;
            float lin = finb + gA0.z + gA1.z + gA2.z + gA3.z;
#pragma unroll
            for (int c = 0; c < 8; c++) {
                float e = fmaf(xcA[c], cw[c], cbv[c]);
                s += e;
                sq = fmaf(e, e, sq);
                lin += fmaf(xcA[c], clw[c], clb[c]);
            }
            out[(size_t)rA * 32 + lane] = lin + 0.5f * (s * s - sq);
            float a0 = cb0 + gA0.x + gA1.x + gA2.x + gA3.x;
            float a1 = cb1 + gA0.y + gA1.y + gA2.y + gA3.y;
#pragma unroll
            for (int c = 0; c < 8; c++) {
                a0 = fmaf(xcA[c], A0[c], a0);
                a1 = fmaf(xcA[c], A1[c], a1);
            }
            g_h1[(size_t)rA * 64 + lane] = a0;
            g_h1[(size_t)rA * 64 + 32 + lane] = a1;
            sum0 += a0; sq0 = fmaf(a0, a0, sq0);
            sum1 += a1; sq1 = fmaf(a1, a1, sq1);
        }
        // row B
        {
            float s = gB0.w + gB1.w + gB2.w + gB3.w;
            float sq = gB0.w * gB0.w + gB1.w * gB1.w + gB2.w * gB2.w + gB3.w * gB3.w;
            float lin = finb + gB0.z + gB1.z + gB2.z + gB3.z;
#pragma unroll
            for (int c = 0; c < 8; c++) {
                float e = fmaf(xcB[c], cw[c], cbv[c]);
                s += e;
                sq = fmaf(e, e, sq);
                lin += fmaf(xcB[c], clw[c], clb[c]);
            }
            out[(size_t)rB * 32 + lane] = lin + 0.5f * (s * s - sq);
            float a0 = cb0 + gB0.x + gB1.x + gB2.x + gB3.x;
            float a1 = cb1 + gB0.y + gB1.y + gB2.y + gB3.y;
#pragma unroll
            for (int c = 0; c < 8; c++) {
                a0 = fmaf(xcB[c], A0[c], a0);
                a1 = fmaf(xcB[c], A1[c], a1);
            }
            g_h1[(size_t)rB * 64 + lane] = a0;
            g_h1[(size_t)rB * 64 + 32 + lane] = a1;
            sum0 += a0; sq0 = fmaf(a0, a0, sq0);
            sum1 += a1; sq1 = fmaf(a1, a1, sq1);
        }
    }

    __shared__ float rs[64][8], rq[64][8];
    rs[lane][warp] = sum0; rs[lane + 32][warp] = sum1;
    rq[lane][warp] = sq0;  rq[lane + 32][warp] = sq1;
    __syncthreads();
    int t = threadIdx.x;
    if (t < 64) {
        float a = 0.f;
#pragma unroll
        for (int w = 0; w < 8; w++) a += rs[t][w];
        g_part1[blockIdx.x * 128 + t] = a;
    } else if (t < 128) {
        float a = 0.f;
#pragma unroll
        for (int w = 0; w < 8; w++) a += rq[t - 64][w];
        g_part1[blockIdx.x * 128 + t] = a;
    }

    __threadfence();
    __shared__ unsigned s_last;
    if (t == 0) {
        unsigned tk = atomicAdd(&g_cnt1, 1u);
        s_last = (tk == gridDim.x - 1) ? 1u : 0u;
    }
    __syncthreads();
    if (s_last) {
        __shared__ float sm[256];
        int ch = t & 127;
        int half = t >> 7;   // 2 slices of 400 blocks
        float a = 0.f;
        int b0 = half * (K1_BLOCKS / 2);
        for (int b = b0; b < b0 + K1_BLOCKS / 2; b++) a += g_part1[b * 128 + ch];
        sm[t] = a;
        __syncthreads();
        if (t < 64) {
            float s = sm[t] + sm[128 + t];
            float q = sm[64 + t] + sm[192 + t];
            float mean = s / (float)NROWS;
            float var = q / (float)NROWS - mean * mean;
            float scale = g1[t] * rsqrtf(var + BN_EPS);
            g_bn1[t] = scale;
            g_bn1[64 + t] = beta1[t] - mean * scale;
        }
        if (t == 0) g_cnt1 = 0;
    }
}

// ---------------------------------------------------------------------------
// Kernel 3: smem-tiled GEMM, FFMA2 with k-pair-packed weights and
// CONSECUTIVE columns per thread (float4 coalesced stores).
// h2 = relu(bn1(h1)) @ w2^T + b2; BN2 partials; last block finalizes.
// wt[kp*32+c] = pack(w2[c][2kp], w2[c][2kp+1]), kp in [0,32).
// ---------------------------------------------------------------------------
__global__ void __launch_bounds__(256) k3(const float* __restrict__ w2,
                                          const float* __restrict__ b2,
                                          const float* __restrict__ g2,
                                          const float* __restrict__ beta2) {
    __shared__ __align__(16) float a[TILE_R * 68];   // bn+relu(h1), stride 68
    __shared__ __align__(16) u64 wt[32 * 32];        // [kp][c]
    __shared__ float sc[64], sh[64];
    __shared__ float wsum[8 * 32], wsq[8 * 32];

    int tid = threadIdx.x;
    int lane = tid & 31, warp = tid >> 5;
    int tr = lane >> 3, tj = lane & 7;
    int j0 = tj * 4;

    // stage w2 (32 cols x 64 K) as k-pair u64s
    for (int i = tid; i < 1024; i += 256) {
        int c = i >> 5, kp = i & 31;    // c in [0,32), kp in [0,32)
        wt[kp * 32 + c] = *(const u64*)&w2[c * 64 + kp * 2];
    }
    if (tid < 64) { sc[tid] = g_bn1[tid]; sh[tid] = g_bn1[64 + tid]; }
    float bj[4];
#pragma unroll
    for (int cc = 0; cc < 4; cc++) bj[cc] = b2[j0 + cc];
    __syncthreads();

    float lsum[4] = {0.f, 0.f, 0.f, 0.f}, lsq[4] = {0.f, 0.f, 0.f, 0.f};
    int rb = warp * 16 + tr;

    for (int tile = blockIdx.x; tile < N_TILES; tile += gridDim.x) {
        size_t base = (size_t)tile * TILE_R;
        for (int i = tid; i < TILE_R * 16; i += 256) {
            int r = i >> 4, c4 = (i & 15) * 4;
            float4 v = *(const float4*)&g_h1[(base + r) * 64 + c4];
            v.x = fmaxf(fmaf(v.x, sc[c4], sh[c4]), 0.f);
            v.y = fmaxf(fmaf(v.y, sc[c4 + 1], sh[c4 + 1]), 0.f);
            v.z = fmaxf(fmaf(v.z, sc[c4 + 2], sh[c4 + 2]), 0.f);
            v.w = fmaxf(fmaf(v.w, sc[c4 + 3], sh[c4 + 3]), 0.f);
            *(float4*)&a[r * 68 + c4] = v;
        }
        __syncthreads();

        u64 accp[4][4];
#pragma unroll
        for (int i = 0; i < 4; i++)
#pragma unroll
            for (int cc = 0; cc < 4; cc++) accp[i][cc] = 0ull;

#pragma unroll
        for (int kq = 0; kq < 16; kq++) {
            ulonglong2 w0a = *(ulonglong2*)&wt[(2 * kq) * 32 + j0];
            ulonglong2 w0b = *(ulonglong2*)&wt[(2 * kq) * 32 + j0 + 2];
            ulonglong2 w1a = *(ulonglong2*)&wt[(2 * kq + 1) * 32 + j0];
            ulonglong2 w1b = *(ulonglong2*)&wt[(2 * kq + 1) * 32 + j0 + 2];
#pragma unroll
            for (int i = 0; i < 4; i++) {
                ulonglong2 av = *(ulonglong2*)&a[(rb + i * 4) * 68 + kq * 4];
                accp[i][0] = fma2(av.x, w0a.x, accp[i][0]);
                accp[i][0] = fma2(av.y, w1a.x, accp[i][0]);
                accp[i][1] = fma2(av.x, w0a.y, accp[i][1]);
                accp[i][1] = fma2(av.y, w1a.y, accp[i][1]);
                accp[i][2] = fma2(av.x, w0b.x, accp[i][2]);
                accp[i][2] = fma2(av.y, w1b.x, accp[i][2]);
                accp[i][3] = fma2(av.x, w0b.y, accp[i][3]);
                accp[i][3] = fma2(av.y, w1b.y, accp[i][3]);
            }
        }

#pragma unroll
        for (int i = 0; i < 4; i++) {
            size_t r = base + rb + i * 4;
            float4 o;
            o.x = f32x2_sum(accp[i][0]) + bj[0];
            o.y = f32x2_sum(accp[i][1]) + bj[1];
            o.z = f32x2_sum(accp[i][2]) + bj[2];
            o.w = f32x2_sum(accp[i][3]) + bj[3];
            *(float4*)&g_h2[r * 32 + j0] = o;
            lsum[0] += o.x; lsq[0] = fmaf(o.x, o.x, lsq[0]);
            lsum[1] += o.y; lsq[1] = fmaf(o.y, o.y, lsq[1]);
            lsum[2] += o.z; lsq[2] = fmaf(o.z, o.z, lsq[2]);
            lsum[3] += o.w; lsq[3] = fmaf(o.w, o.w, lsq[3]);
        }
        __syncthreads();
    }

    // reduce BN2 partials over tr groups (lanes xor 8,16), then across warps
#pragma unroll
    for (int cc = 0; cc < 4; cc++) {
        lsum[cc] += __shfl_xor_sync(0xffffffffu, lsum[cc], 8);
        lsum[cc] += __shfl_xor_sync(0xffffffffu, lsum[cc], 16);
        lsq[cc] += __shfl_xor_sync(0xffffffffu, lsq[cc], 8);
        lsq[cc] += __shfl_xor_sync(0xffffffffu, lsq[cc], 16);
    }
    if (tr == 0) {
#pragma unroll
        for (int cc = 0; cc < 4; cc++) {
            wsum[warp * 32 + j0 + cc] = lsum[cc];
            wsq[warp * 32 + j0 + cc] = lsq[cc];
        }
    }
    __syncthreads();
    int t = tid;
    if (t < 32) {
        float s = 0.f;
#pragma unroll
        for (int w = 0; w < 8; w++) s += wsum[w * 32 + t];
        g_part2[blockIdx.x * 64 + t] = s;
    } else if (t < 64) {
        float q = 0.f;
#pragma unroll
        for (int w = 0; w < 8; w++) q += wsq[w * 32 + (t - 32)];
        g_part2[blockIdx.x * 64 + t] = q;
    }

    __threadfence();
    __shared__ unsigned s_last;
    if (t == 0) {
        unsigned tk = atomicAdd(&g_cnt2, 1u);
        s_last = (tk == gridDim.x - 1) ? 1u : 0u;
    }
    __syncthreads();
    if (s_last) {
        __shared__ float sm[256];
        int ch = t & 63;
        int sl = t >> 6;   // 4 slices of K3_GRID/4 = 111
        float aa = 0.f;
        int b0 = sl * (K3_GRID / 4);
        for (int b = b0; b < b0 + K3_GRID / 4; b++) aa += g_part2[b * 64 + ch];
        sm[t] = aa;
        __syncthreads();
        if (t < 32) {
            float s = (sm[t] + sm[64 + t]) + (sm[128 + t] + sm[192 + t]);
            float q = (sm[32 + t] + sm[96 + t]) + (sm[160 + t] + sm[224 + t]);
            float mean = s / (float)NROWS;
            float var = q / (float)NROWS - mean * mean;
            float scale = g2[t] * rsqrtf(var + BN_EPS);
            g_bn2[t] = scale;
            g_bn2[32 + t] = beta2[t] - mean * scale;
        }
        if (t == 0) g_cnt2 = 0;
    }
}

// ---------------------------------------------------------------------------
// Kernel 5: smem-tiled GEMM, FFMA2, float4 RMW epilogue.
// out += relu(bn2(h2)) @ w_out^T + b_out. wt[kp*32+c], kp in [0,16).
// ---------------------------------------------------------------------------
__global__ void __launch_bounds__(256) k5(const float* __restrict__ wout,
                                          const float* __restrict__ bout,
                                          float* __restrict__ out) {
    __shared__ __align__(16) float a[TILE_R * 36];   // bn+relu(h2), stride 36
    __shared__ __align__(16) u64 wt[16 * 32];
    __shared__ float sc[32], sh[32];

    int tid = threadIdx.x;
    int lane = tid & 31, warp = tid >> 5;
    int tr = lane >> 3, tj = lane & 7;
    int j0 = tj * 4;

    for (int i = tid; i < 512; i += 256) {
        int c = i >> 4, kp = i & 15;    // c in [0,32), kp in [0,16)
        wt[kp * 32 + c] = *(const u64*)&wout[c * 32 + kp * 2];
    }
    if (tid < 32) { sc[tid] = g_bn2[tid]; sh[tid] = g_bn2[32 + tid]; }
    float bj[4];
#pragma unroll
    for (int cc = 0; cc < 4; cc++) bj[cc] = bout[j0 + cc];
    __syncthreads();

    int rb = warp * 16 + tr;

    for (int tile = blockIdx.x; tile < N_TILES; tile += gridDim.x) {
        size_t base = (size_t)tile * TILE_R;
        for (int i = tid; i < TILE_R * 8; i += 256) {
            int r = i >> 3, c4 = (i & 7) * 4;
            float4 v = *(const float4*)&g_h2[(base + r) * 32 + c4];
            v.x = fmaxf(fmaf(v.x, sc[c4], sh[c4]), 0.f);
            v.y = fmaxf(fmaf(v.y, sc[c4 + 1], sh[c4 + 1]), 0.f);
            v.z = fmaxf(fmaf(v.z, sc[c4 + 2], sh[c4 + 2]), 0.f);
            v.w = fmaxf(fmaf(v.w, sc[c4 + 3], sh[c4 + 3]), 0.f);
            *(float4*)&a[r * 36 + c4] = v;
        }
        __syncthreads();

        u64 accp[4][4];
#pragma unroll
        for (int i = 0; i < 4; i++)
#pragma unroll
            for (int cc = 0; cc < 4; cc++) accp[i][cc] = 0ull;

#pragma unroll
        for (int kq = 0; kq < 8; kq++) {
            ulonglong2 w0a = *(ulonglong2*)&wt[(2 * kq) * 32 + j0];
            ulonglong2 w0b = *(ulonglong2*)&wt[(2 * kq) * 32 + j0 + 2];
            ulonglong2 w1a = *(ulonglong2*)&wt[(2 * kq + 1) * 32 + j0];
            ulonglong2 w1b = *(ulonglong2*)&wt[(2 * kq + 1) * 32 + j0 + 2];
#pragma unroll
            for (int i = 0; i < 4; i++) {
                ulonglong2 av = *(ulonglong2*)&a[(rb + i * 4) * 36 + kq * 4];
                accp[i][0] = fma2(av.x, w0a.x, accp[i][0]);
                accp[i][0] = fma2(av.y, w1a.x, accp[i][0]);
                accp[i][1] = fma2(av.x, w0a.y, accp[i][1]);
                accp[i][1] = fma2(av.y, w1a.y, accp[i][1]);
                accp[i][2] = fma2(av.x, w0b.x, accp[i][2]);
                accp[i][2] = fma2(av.y, w1b.x, accp[i][2]);
                accp[i][3] = fma2(av.x, w0b.y, accp[i][3]);
                accp[i][3] = fma2(av.y, w1b.y, accp[i][3]);
            }
        }

#pragma unroll
        for (int i = 0; i < 4; i++) {
            size_t r = base + rb + i * 4;
            float4 o = *(const float4*)&out[r * 32 + j0];
            o.x += f32x2_sum(accp[i][0]) + bj[0];
            o.y += f32x2_sum(accp[i][1]) + bj[1];
            o.z += f32x2_sum(accp[i][2]) + bj[2];
            o.w += f32x2_sum(accp[i][3]) + bj[3];
            *(float4*)&out[r * 32 + j0] = o;
        }
        __syncthreads();
    }
}

// ---------------------------------------------------------------------------
// Input order (setup_inputs dict insertion): x, emb0, lin0, emb1, lin1,
// emb2, lin2, emb3, lin3, cont_w, cont_b, clin_w, clin_b, fin_bias,
// w1, b1, g1, beta1, w2, b2, g2, beta2, w_out, b_out
// ---------------------------------------------------------------------------
extern "C" void kernel_launch(void* const* d_in, const int* in_sizes, int n_in,
                              void* d_out, int out_size) {
    const float* x      = (const float*)d_in[0];
    const float* emb0   = (const float*)d_in[1];
    const float* lin0   = (const float*)d_in[2];
    const float* emb1   = (const float*)d_in[3];
    const float* lin1   = (const float*)d_in[4];
    const float* emb2   = (const float*)d_in[5];
    const float* lin2   = (const float*)d_in[6];
    const float* emb3   = (const float*)d_in[7];
    const float* lin3   = (const float*)d_in[8];
    const float* cont_w = (const float*)d_in[9];
    const float* cont_b = (const float*)d_in[10];
    const float* clin_w = (const float*)d_in[11];
    const float* clin_b = (const float*)d_in[12];
    const float* fin_b  = (const float*)d_in[13];
    const float* w1     = (const float*)d_in[14];
    const float* b1     = (const float*)d_in[15];
    const float* g1     = (const float*)d_in[16];
    const float* beta1  = (const float*)d_in[17];
    const float* w2     = (const float*)d_in[18];
    const float* b2     = (const float*)d_in[19];
    const float* g2     = (const float*)d_in[20];
    const float* beta2  = (const float*)d_in[21];
    const float* w_out  = (const float*)d_in[22];
    const float* b_out  = (const float*)d_in[23];
    float* out = (float*)d_out;

    kSetup<<<SETUP_BLOCKS, 256>>>(emb0, emb1, emb2, emb3,
                                  lin0, lin1, lin2, lin3,
                                  w1, b1, cont_w, cont_b);
    k1<<<K1_BLOCKS, 256>>>(x, cont_w, cont_b, clin_w, clin_b, fin_b,
                           g1, beta1, out);
    k3<<<K3_GRID, 256>>>(w2, b2, g2, beta2);
    k5<<<K5_GRID, 256>>>(w_out, b_out, out);
}

// round 9
// speedup vs baseline: 1.0648x; 1.0648x over previous
#include <cuda_runtime.h>
#include <cuda_fp16.h>

#define NROWS 204800
#define BN_EPS 1e-5f

#define FD0 100000
#define FD1 1000
#define FD2 100
#define FD3 50
#define PV (FD0 + FD1 + FD2 + FD3)
#define GOFF1 FD0
#define GOFF2 (FD0 + FD1)
#define GOFF3 (FD0 + FD1 + FD2)

#define K1_BLOCKS 800
#define K3_GRID 592
#define K5_GRID 592
#define SETUP_BLOCKS 512
#define TILE_R 128
#define N_TILES (NROWS / TILE_R)   // 1600

__device__ __forceinline__ unsigned h2u(__half2 h) {
    return *reinterpret_cast<unsigned*>(&h);
}

// Scratch (device globals; no runtime allocation allowed)
__device__ float4 g_G[(size_t)PV * 32];           // fused gather table (P_lo,P_hi,lin,emb)
__device__ float g_A[64 * 8];                     // cont_w folded into w1
__device__ float g_cb[64];                        // b1 + cont_b folded into w1
__device__ __half2 g_h1h[(size_t)NROWS * 32];     // h1 fp16: [r][c] = (col c, col c+32)
__device__ __half g_h2h[(size_t)NROWS * 32];      // h2 fp16 row-major
__device__ float g_part1[K1_BLOCKS * 128];        // per-block BN1 partials
__device__ float g_part2[K3_GRID * 64];           // per-block BN2 partials
__device__ float g_bn1[128];                      // scale[64], shift[64]
__device__ float g_bn2[64];                       // scale[32], shift[32]
__device__ unsigned g_cnt1 = 0;
__device__ unsigned g_cnt2 = 0;

// ---------------------------------------------------------------------------
// kSetup: cont-fold init AND the fused gather table for all 4 fields.
// g_G[(gOff+v)*32+lane] = (P[v][lane], P[v][lane+32], lin[v][lane], emb[v][lane])
// ---------------------------------------------------------------------------
__global__ void __launch_bounds__(256) kSetup(
    const float* __restrict__ emb0, const float* __restrict__ emb1,
    const float* __restrict__ emb2, const float* __restrict__ emb3,
    const float* __restrict__ lin0, const float* __restrict__ lin1,
    const float* __restrict__ lin2, const float* __restrict__ lin3,
    const float* __restrict__ w1, const float* __restrict__ b1,
    const float* __restrict__ cont_w, const float* __restrict__ cont_b) {
    int bid = blockIdx.x;
    int lane = threadIdx.x & 31;
    int warp = threadIdx.x >> 5;

    if (bid == 511) {  // cont-feature fold into w1
        int j = threadIdx.x;
        if (j < 64) {
            float cb = b1[j];
            for (int c = 0; c < 8; c++) {
                float a = 0.f;
#pragma unroll
                for (int d = 0; d < 32; d++) {
                    float w = w1[j * 384 + (4 + c) * 32 + d];
                    a = fmaf(cont_w[c * 32 + d], w, a);
                    cb = fmaf(cont_b[c * 32 + d], w, cb);
                }
                g_A[j * 8 + c] = a;
            }
            g_cb[j] = cb;
        }
        return;
    }

    const float* emb;
    const float* lin;
    int V, gOff, colOff, wfirst, nwarp;
    if (bid < 506) {
        emb = emb0; lin = lin0; V = FD0; gOff = 0; colOff = 0;
        wfirst = bid * 8 + warp; nwarp = 506 * 8;
    } else if (bid < 510) {
        emb = emb1; lin = lin1; V = FD1; gOff = GOFF1; colOff = 32;
        wfirst = (bid - 506) * 8 + warp; nwarp = 32;
    } else if (warp < 4) {
        emb = emb2; lin = lin2; V = FD2; gOff = GOFF2; colOff = 64;
        wfirst = warp; nwarp = 4;
    } else {
        emb = emb3; lin = lin3; V = FD3; gOff = GOFF3; colOff = 96;
        wfirst = warp - 4; nwarp = 4;
    }

    float wa[32], wb[32];
#pragma unroll
    for (int d = 0; d < 32; d++) {
        wa[d] = w1[lane * 384 + colOff + d];
        wb[d] = w1[(lane + 32) * 384 + colOff + d];
    }
    for (int v = wfirst; v < V; v += nwarp) {
        float ev = emb[v * 32 + lane];
        float lv = lin[v * 32 + lane];
        float a0 = 0.f, a1 = 0.f;
#pragma unroll
        for (int d = 0; d < 32; d++) {
            float e = __shfl_sync(0xffffffffu, ev, d);
            a0 = fmaf(e, wa[d], a0);
            a1 = fmaf(e, wb[d], a1);
        }
        g_G[(size_t)(gOff + v) * 32 + lane] = make_float4(a0, a1, lv, ev);
    }
}

// ---------------------------------------------------------------------------
// Kernel 1: contiguous 32-row chunk per warp, 2 rows per iteration,
// one LDG.128 per (feature,row). FM + linear -> out; h1 -> fp16; BN1
// partials; last block finalizes BN1.
// ---------------------------------------------------------------------------
__global__ void __launch_bounds__(256) k1(
    const float* __restrict__ x,
    const float* __restrict__ cont_w, const float* __restrict__ cont_b,
    const float* __restrict__ clin_w, const float* __restrict__ clin_b,
    const float* __restrict__ fin_bias,
    const float* __restrict__ g1, const float* __restrict__ beta1,
    float* __restrict__ out) {
    int lane = threadIdx.x & 31;
    int warp = threadIdx.x >> 5;
    int gw = blockIdx.x * 8 + warp;          // 6400 warps x 32 rows = NROWS
    int rbase = gw * 32;

    float cw[8], cbv[8], clw[8], clb[8], A0[8], A1[8];
#pragma unroll
    for (int c = 0; c < 8; c++) {
        cw[c] = cont_w[c * 32 + lane];
        cbv[c] = cont_b[c * 32 + lane];
        clw[c] = clin_w[c * 32 + lane];
        clb[c] = clin_b[c * 32 + lane];
        A0[c] = g_A[lane * 8 + c];
        A1[c] = g_A[(lane + 32) * 8 + c];
    }
    float finb = fin_bias[lane];
    float cb0 = g_cb[lane], cb1 = g_cb[lane + 32];
    float sum0 = 0.f, sq0 = 0.f, sum1 = 0.f, sq1 = 0.f;

    for (int it = 0; it < 16; it++) {
        int rA = rbase + it * 2;
        int rB = rA + 1;
        float xv = 0.f;
        if (lane < 24) xv = x[rA * 12 + lane];
        int iA0 = (int)__shfl_sync(0xffffffffu, xv, 0);
        int iA1 = (int)__shfl_sync(0xffffffffu, xv, 1);
        int iA2 = (int)__shfl_sync(0xffffffffu, xv, 2);
        int iA3 = (int)__shfl_sync(0xffffffffu, xv, 3);
        int iB0 = (int)__shfl_sync(0xffffffffu, xv, 12);
        int iB1 = (int)__shfl_sync(0xffffffffu, xv, 13);
        int iB2 = (int)__shfl_sync(0xffffffffu, xv, 14);
        int iB3 = (int)__shfl_sync(0xffffffffu, xv, 15);
        float xcA[8], xcB[8];
#pragma unroll
        for (int c = 0; c < 8; c++) {
            xcA[c] = __shfl_sync(0xffffffffu, xv, 4 + c);
            xcB[c] = __shfl_sync(0xffffffffu, xv, 16 + c);
        }

        float4 gA0 = g_G[(size_t)iA0 * 32 + lane];
        float4 gA1 = g_G[(size_t)(GOFF1 + iA1) * 32 + lane];
        float4 gA2 = g_G[(size_t)(GOFF2 + iA2) * 32 + lane];
        float4 gA3 = g_G[(size_t)(GOFF3 + iA3) * 32 + lane];
        float4 gB0 = g_G[(size_t)iB0 * 32 + lane];
        float4 gB1 = g_G[(size_t)(GOFF1 + iB1) * 32 + lane];
        float4 gB2 = g_G[(size_t)(GOFF2 + iB2) * 32 + lane];
        float4 gB3 = g_G[(size_t)(GOFF3 + iB3) * 32 + lane];

        // row A
        {
            float s = gA0.w + gA1.w + gA2.w + gA3.w;
            float sq = gA0.w * gA0.w + gA1.w * gA1.w + gA2.w * gA2.w + gA3.w * gA3.w;
            float lin = finb + gA0.z + gA1.z + gA2.z + gA3.z;
#pragma unroll
            for (int c = 0; c < 8; c++) {
                float e = fmaf(xcA[c], cw[c], cbv[c]);
                s += e;
                sq = fmaf(e, e, sq);
                lin += fmaf(xcA[c], clw[c], clb[c]);
            }
            out[(size_t)rA * 32 + lane] = lin + 0.5f * (s * s - sq);
            float a0 = cb0 + gA0.x + gA1.x + gA2.x + gA3.x;
            float a1 = cb1 + gA0.y + gA1.y + gA2.y + gA3.y;
#pragma unroll
            for (int c = 0; c < 8; c++) {
                a0 = fmaf(xcA[c], A0[c], a0);
                a1 = fmaf(xcA[c], A1[c], a1);
            }
            g_h1h[(size_t)rA * 32 + lane] = __floats2half2_rn(a0, a1);
            sum0 += a0; sq0 = fmaf(a0, a0, sq0);
            sum1 += a1; sq1 = fmaf(a1, a1, sq1);
        }
        // row B
        {
            float s = gB0.w + gB1.w + gB2.w + gB3.w;
            float sq = gB0.w * gB0.w + gB1.w * gB1.w + gB2.w * gB2.w + gB3.w * gB3.w;
            float lin = finb + gB0.z + gB1.z + gB2.z + gB3.z;
#pragma unroll
            for (int c = 0; c < 8; c++) {
                float e = fmaf(xcB[c], cw[c], cbv[c]);
                s += e;
                sq = fmaf(e, e, sq);
                lin += fmaf(xcB[c], clw[c], clb[c]);
            }
            out[(size_t)rB * 32 + lane] = lin + 0.5f * (s * s - sq);
            float a0 = cb0 + gB0.x + gB1.x + gB2.x + gB3.x;
            float a1 = cb1 + gB0.y + gB1.y + gB2.y + gB3.y;
#pragma unroll
            for (int c = 0; c < 8; c++) {
                a0 = fmaf(xcB[c], A0[c], a0);
                a1 = fmaf(xcB[c], A1[c], a1);
            }
            g_h1h[(size_t)rB * 32 + lane] = __floats2half2_rn(a0, a1);
            sum0 += a0; sq0 = fmaf(a0, a0, sq0);
            sum1 += a1; sq1 = fmaf(a1, a1, sq1);
        }
    }

    __shared__ float rs[64][8], rq[64][8];
    rs[lane][warp] = sum0; rs[lane + 32][warp] = sum1;
    rq[lane][warp] = sq0;  rq[lane + 32][warp] = sq1;
    __syncthreads();
    int t = threadIdx.x;
    if (t < 64) {
        float a = 0.f;
#pragma unroll
        for (int w = 0; w < 8; w++) a += rs[t][w];
        g_part1[blockIdx.x * 128 + t] = a;
    } else if (t < 128) {
        float a = 0.f;
#pragma unroll
        for (int w = 0; w < 8; w++) a += rq[t - 64][w];
        g_part1[blockIdx.x * 128 + t] = a;
    }

    __threadfence();
    __shared__ unsigned s_last;
    if (t == 0) {
        unsigned tk = atomicAdd(&g_cnt1, 1u);
        s_last = (tk == gridDim.x - 1) ? 1u : 0u;
    }
    __syncthreads();
    if (s_last) {
        __shared__ float sm[256];
        int ch = t & 127;
        int half = t >> 7;   // 2 slices of 400 blocks
        float a = 0.f;
        int b0 = half * (K1_BLOCKS / 2);
        for (int b = b0; b < b0 + K1_BLOCKS / 2; b++) a += g_part1[b * 128 + ch];
        sm[t] = a;
        __syncthreads();
        if (t < 64) {
            float s = sm[t] + sm[128 + t];
            float q = sm[64 + t] + sm[192 + t];
            float mean = s / (float)NROWS;
            float var = q / (float)NROWS - mean * mean;
            float scale = g1[t] * rsqrtf(var + BN_EPS);
            g_bn1[t] = scale;
            g_bn1[64 + t] = beta1[t] - mean * scale;
        }
        if (t == 0) g_cnt1 = 0;
    }
}

// ---------------------------------------------------------------------------
// Kernel 3: smem-tiled plain-FFMA GEMM (R4 structure).
// h2 = relu(bn1(h1)) @ w2^T + b2; h1 read fp16, h2 written fp16.
// Thread: 4 rows x 4 consecutive cols. BN2 partials; last block finalizes.
// ---------------------------------------------------------------------------
__global__ void __launch_bounds__(256) k3(const float* __restrict__ w2,
                                          const float* __restrict__ b2,
                                          const float* __restrict__ g2,
                                          const float* __restrict__ beta2) {
    __shared__ __align__(16) float a[TILE_R * 68];   // bn+relu(h1), stride 68
    __shared__ float wt[64 * 36];                    // w2^T: wt[k*36+j]
    __shared__ float sc[64], sh[64];
    __shared__ float wsum[8 * 32], wsq[8 * 32];

    int tid = threadIdx.x;
    int lane = tid & 31, warp = tid >> 5;
    int tr = lane >> 3, tj = lane & 7;
    int j0 = tj * 4;

    for (int i = tid; i < 2048; i += 256) {
        int j = i >> 6, k = i & 63;
        wt[k * 36 + j] = w2[i];
    }
    if (tid < 64) { sc[tid] = g_bn1[tid]; sh[tid] = g_bn1[64 + tid]; }
    float bj[4];
#pragma unroll
    for (int c = 0; c < 4; c++) bj[c] = b2[j0 + c];
    __syncthreads();

    float lsum[4] = {0.f, 0.f, 0.f, 0.f}, lsq[4] = {0.f, 0.f, 0.f, 0.f};
    int rbase = warp * 16 + tr;

    for (int tile = blockIdx.x; tile < N_TILES; tile += gridDim.x) {
        size_t base = (size_t)tile * TILE_R;
        // stage: read fp16 (c,c+32) pairs, apply bn1+relu, store fp32 smem
        for (int i = tid; i < TILE_R * 8; i += 256) {
            int r = i >> 3, c4 = (i & 7) * 4;
            uint4 raw = *(const uint4*)&g_h1h[(base + r) * 32 + c4];
            const __half2* hp = (const __half2*)&raw;
            float lo[4], hi[4];
#pragma unroll
            for (int m = 0; m < 4; m++) {
                float2 f = __half22float2(hp[m]);
                lo[m] = fmaxf(fmaf(f.x, sc[c4 + m], sh[c4 + m]), 0.f);
                hi[m] = fmaxf(fmaf(f.y, sc[c4 + m + 32], sh[c4 + m + 32]), 0.f);
            }
            *(float4*)&a[r * 68 + c4] = make_float4(lo[0], lo[1], lo[2], lo[3]);
            *(float4*)&a[r * 68 + 32 + c4] = make_float4(hi[0], hi[1], hi[2], hi[3]);
        }
        __syncthreads();

        float acc[4][4];
#pragma unroll
        for (int i = 0; i < 4; i++)
#pragma unroll
            for (int c = 0; c < 4; c++) acc[i][c] = 0.f;

#pragma unroll 4
        for (int k = 0; k < 64; k += 4) {
            float4 w0 = *(float4*)&wt[(k + 0) * 36 + j0];
            float4 w1v = *(float4*)&wt[(k + 1) * 36 + j0];
            float4 w2v = *(float4*)&wt[(k + 2) * 36 + j0];
            float4 w3 = *(float4*)&wt[(k + 3) * 36 + j0];
#pragma unroll
            for (int i = 0; i < 4; i++) {
                float4 av = *(float4*)&a[(rbase + i * 4) * 68 + k];
                acc[i][0] = fmaf(av.x, w0.x, acc[i][0]);
                acc[i][1] = fmaf(av.x, w0.y, acc[i][1]);
                acc[i][2] = fmaf(av.x, w0.z, acc[i][2]);
                acc[i][3] = fmaf(av.x, w0.w, acc[i][3]);
                acc[i][0] = fmaf(av.y, w1v.x, acc[i][0]);
                acc[i][1] = fmaf(av.y, w1v.y, acc[i][1]);
                acc[i][2] = fmaf(av.y, w1v.z, acc[i][2]);
                acc[i][3] = fmaf(av.y, w1v.w, acc[i][3]);
                acc[i][0] = fmaf(av.z, w2v.x, acc[i][0]);
                acc[i][1] = fmaf(av.z, w2v.y, acc[i][1]);
                acc[i][2] = fmaf(av.z, w2v.z, acc[i][2]);
                acc[i][3] = fmaf(av.z, w2v.w, acc[i][3]);
                acc[i][0] = fmaf(av.w, w3.x, acc[i][0]);
                acc[i][1] = fmaf(av.w, w3.y, acc[i][1]);
                acc[i][2] = fmaf(av.w, w3.z, acc[i][2]);
                acc[i][3] = fmaf(av.w, w3.w, acc[i][3]);
            }
        }

#pragma unroll
        for (int i = 0; i < 4; i++) {
            size_t r = base + rbase + i * 4;
            float v0 = acc[i][0] + bj[0];
            float v1 = acc[i][1] + bj[1];
            float v2 = acc[i][2] + bj[2];
            float v3 = acc[i][3] + bj[3];
            uint2 pk;
            pk.x = h2u(__floats2half2_rn(v0, v1));
            pk.y = h2u(__floats2half2_rn(v2, v3));
            *(uint2*)&g_h2h[r * 32 + j0] = pk;
            lsum[0] += v0; lsq[0] = fmaf(v0, v0, lsq[0]);
            lsum[1] += v1; lsq[1] = fmaf(v1, v1, lsq[1]);
            lsum[2] += v2; lsq[2] = fmaf(v2, v2, lsq[2]);
            lsum[3] += v3; lsq[3] = fmaf(v3, v3, lsq[3]);
        }
        __syncthreads();
    }

    // reduce BN2 partials over tr groups (lanes xor 8,16), then across warps
#pragma unroll
    for (int c = 0; c < 4; c++) {
        lsum[c] += __shfl_xor_sync(0xffffffffu, lsum[c], 8);
        lsum[c] += __shfl_xor_sync(0xffffffffu, lsum[c], 16);
        lsq[c] += __shfl_xor_sync(0xffffffffu, lsq[c], 8);
        lsq[c] += __shfl_xor_sync(0xffffffffu, lsq[c], 16);
    }
    if (tr == 0) {
#pragma unroll
        for (int c = 0; c < 4; c++) {
            wsum[warp * 32 + j0 + c] = lsum[c];
            wsq[warp * 32 + j0 + c] = lsq[c];
        }
    }
    __syncthreads();
    int t = tid;
    if (t < 32) {
        float s = 0.f;
#pragma unroll
        for (int w = 0; w < 8; w++) s += wsum[w * 32 + t];
        g_part2[blockIdx.x * 64 + t] = s;
    } else if (t < 64) {
        float q = 0.f;
#pragma unroll
        for (int w = 0; w < 8; w++) q += wsq[w * 32 + (t - 32)];
        g_part2[blockIdx.x * 64 + t] = q;
    }

    __threadfence();
    __shared__ unsigned s_last;
    if (t == 0) {
        unsigned tk = atomicAdd(&g_cnt2, 1u);
        s_last = (tk == gridDim.x - 1) ? 1u : 0u;
    }
    __syncthreads();
    if (s_last) {
        __shared__ float sm[256];
        int ch = t & 63;
        int sl = t >> 6;   // 4 slices of 148
        float aa = 0.f;
        int b0 = sl * (K3_GRID / 4);
        for (int b = b0; b < b0 + K3_GRID / 4; b++) aa += g_part2[b * 64 + ch];
        sm[t] = aa;
        __syncthreads();
        if (t < 32) {
            float s = (sm[t] + sm[64 + t]) + (sm[128 + t] + sm[192 + t]);
            float q = (sm[32 + t] + sm[96 + t]) + (sm[160 + t] + sm[224 + t]);
            float mean = s / (float)NROWS;
            float var = q / (float)NROWS - mean * mean;
            float scale = g2[t] * rsqrtf(var + BN_EPS);
            g_bn2[t] = scale;
            g_bn2[32 + t] = beta2[t] - mean * scale;
        }
        if (t == 0) g_cnt2 = 0;
    }
}

// ---------------------------------------------------------------------------
// Kernel 5: smem-tiled plain-FFMA GEMM (R4 structure), h2 read fp16.
// out += relu(bn2(h2)) @ w_out^T + b_out.
// ---------------------------------------------------------------------------
__global__ void __launch_bounds__(256) k5(const float* __restrict__ wout,
                                          const float* __restrict__ bout,
                                          float* __restrict__ out) {
    __shared__ __align__(16) float a[TILE_R * 36];   // bn+relu(h2), stride 36
    __shared__ float wt[32 * 36];                    // wout^T: wt[k*36+j]
    __shared__ float sc[32], sh[32];

    int tid = threadIdx.x;
    int lane = tid & 31, warp = tid >> 5;
    int tr = lane >> 3, tj = lane & 7;
    int j0 = tj * 4;

    for (int i = tid; i < 1024; i += 256) {
        int j = i >> 5, k = i & 31;
        wt[k * 36 + j] = wout[i];
    }
    if (tid < 32) { sc[tid] = g_bn2[tid]; sh[tid] = g_bn2[32 + tid]; }
    float bj[4];
#pragma unroll
    for (int c = 0; c < 4; c++) bj[c] = bout[j0 + c];
    __syncthreads();

    int rbase = warp * 16 + tr;

    for (int tile = blockIdx.x; tile < N_TILES; tile += gridDim.x) {
        size_t base = (size_t)tile * TILE_R;
        // stage: read 8 fp16 per uint4, apply bn2+relu, store fp32 smem
        for (int i = tid; i < TILE_R * 4; i += 256) {
            int r = i >> 2, c8 = (i & 3) * 8;
            uint4 raw = *(const uint4*)&g_h2h[(base + r) * 32 + c8];
            const __half2* hp = (const __half2*)&raw;
            float f[8];
#pragma unroll
            for (int m = 0; m < 4; m++) {
                float2 p = __half22float2(hp[m]);
                f[2 * m] = p.x;
                f[2 * m + 1] = p.y;
            }
#pragma unroll
            for (int m = 0; m < 8; m++)
                f[m] = fmaxf(fmaf(f[m], sc[c8 + m], sh[c8 + m]), 0.f);
            *(float4*)&a[r * 36 + c8] = make_float4(f[0], f[1], f[2], f[3]);
            *(float4*)&a[r * 36 + c8 + 4] = make_float4(f[4], f[5], f[6], f[7]);
        }
        __syncthreads();

        float acc[4][4];
#pragma unroll
        for (int i = 0; i < 4; i++)
#pragma unroll
            for (int c = 0; c < 4; c++) acc[i][c] = 0.f;

#pragma unroll 4
        for (int k = 0; k < 32; k += 4) {
            float4 w0 = *(float4*)&wt[(k + 0) * 36 + j0];
            float4 w1v = *(float4*)&wt[(k + 1) * 36 + j0];
            float4 w2v = *(float4*)&wt[(k + 2) * 36 + j0];
            float4 w3 = *(float4*)&wt[(k + 3) * 36 + j0];
#pragma unroll
            for (int i = 0; i < 4; i++) {
                float4 av = *(float4*)&a[(rbase + i * 4) * 36 + k];
                acc[i][0] = fmaf(av.x, w0.x, acc[i][0]);
                acc[i][1] = fmaf(av.x, w0.y, acc[i][1]);
                acc[i][2] = fmaf(av.x, w0.z, acc[i][2]);
                acc[i][3] = fmaf(av.x, w0.w, acc[i][3]);
                acc[i][0] = fmaf(av.y, w1v.x, acc[i][0]);
                acc[i][1] = fmaf(av.y, w1v.y, acc[i][1]);
                acc[i][2] = fmaf(av.y, w1v.z, acc[i][2]);
                acc[i][3] = fmaf(av.y, w1v.w, acc[i][3]);
                acc[i][0] = fmaf(av.z, w2v.x, acc[i][0]);
                acc[i][1] = fmaf(av.z, w2v.y, acc[i][1]);
                acc[i][2] = fmaf(av.z, w2v.z, acc[i][2]);
                acc[i][3] = fmaf(av.z, w2v.w, acc[i][3]);
                acc[i][0] = fmaf(av.w, w3.x, acc[i][0]);
                acc[i][1] = fmaf(av.w, w3.y, acc[i][1]);
                acc[i][2] = fmaf(av.w, w3.z, acc[i][2]);
                acc[i][3] = fmaf(av.w, w3.w, acc[i][3]);
            }
        }

#pragma unroll
        for (int i = 0; i < 4; i++) {
            size_t r = base + rbase + i * 4;
            float4 o = *(const float4*)&out[r * 32 + j0];
            o.x += acc[i][0] + bj[0];
            o.y += acc[i][1] + bj[1];
            o.z += acc[i][2] + bj[2];
            o.w += acc[i][3] + bj[3];
            *(float4*)&out[r * 32 + j0] = o;
        }
        __syncthreads();
    }
}

// ---------------------------------------------------------------------------
// Input order (setup_inputs dict insertion): x, emb0, lin0, emb1, lin1,
// emb2, lin2, emb3, lin3, cont_w, cont_b, clin_w, clin_b, fin_bias,
// w1, b1, g1, beta1, w2, b2, g2, beta2, w_out, b_out
// ---------------------------------------------------------------------------
extern "C" void kernel_launch(void* const* d_in, const int* in_sizes, int n_in,
                              void* d_out, int out_size) {
    const float* x      = (const float*)d_in[0];
    const float* emb0   = (const float*)d_in[1];
    const float* lin0   = (const float*)d_in[2];
    const float* emb1   = (const float*)d_in[3];
    const float* lin1   = (const float*)d_in[4];
    const float* emb2   = (const float*)d_in[5];
    const float* lin2   = (const float*)d_in[6];
    const float* emb3   = (const float*)d_in[7];
    const float* lin3   = (const float*)d_in[8];
    const float* cont_w = (const float*)d_in[9];
    const float* cont_b = (const float*)d_in[10];
    const float* clin_w = (const float*)d_in[11];
    const float* clin_b = (const float*)d_in[12];
    const float* fin_b  = (const float*)d_in[13];
    const float* w1     = (const float*)d_in[14];
    const float* b1     = (const float*)d_in[15];
    const float* g1     = (const float*)d_in[16];
    const float* beta1  = (const float*)d_in[17];
    const float* w2     = (const float*)d_in[18];
    const float* b2     = (const float*)d_in[19];
    const float* g2     = (const float*)d_in[20];
    const float* beta2  = (const float*)d_in[21];
    const float* w_out  = (const float*)d_in[22];
    const float* b_out  = (const float*)d_in[23];
    float* out = (float*)d_out;

    kSetup<<<SETUP_BLOCKS, 256>>>(emb0, emb1, emb2, emb3,
                                  lin0, lin1, lin2, lin3,
                                  w1, b1, cont_w, cont_b);
    k1<<<K1_BLOCKS, 256>>>(x, cont_w, cont_b, clin_w, clin_b, fin_b,
                           g1, beta1, out);
    k3<<<K3_GRID, 256>>>(w2, b2, g2, beta2);
    k5<<<K5_GRID, 256>>>(w_out, b_out, out);
}

// round 10
// speedup vs baseline: 1.2186x; 1.1445x over previous
#include <cuda_runtime.h>
#include <cuda_fp16.h>

#define NROWS 204800
#define BN_EPS 1e-5f

#define FD0 100000
#define FD1 1000
#define FD2 100
#define FD3 50
#define PV (FD0 + FD1 + FD2 + FD3)
#define GOFF1 FD0
#define GOFF2 (FD0 + FD1)
#define GOFF3 (FD0 + FD1 + FD2)

#define K1_BLOCKS 800
#define K3_GRID 592
#define K5_GRID 592
#define SETUP_BLOCKS 512
#define TILE_R 128
#define N_TILES (NROWS / TILE_R)   // 1600

__device__ __forceinline__ unsigned h2u(__half2 h) {
    return *reinterpret_cast<unsigned*>(&h);
}
__device__ __forceinline__ __half2 u2h(unsigned u) {
    return *reinterpret_cast<__half2*>(&u);
}

// Scratch (device globals; no runtime allocation allowed)
__device__ uint2 g_Gh[(size_t)PV * 32];           // fp16 fused table: (P_lo,P_hi | lin,emb)
__device__ float g_A[64 * 8];                     // cont_w folded into w1
__device__ float g_cb[64];                        // b1 + cont_b folded into w1
__device__ __half2 g_h1h[(size_t)NROWS * 32];     // h1 fp16: [r][c] = (col c, col c+32)
__device__ __half g_h2h[(size_t)NROWS * 32];      // h2 fp16 row-major
__device__ float g_part1[K1_BLOCKS * 128];        // per-block BN1 partials
__device__ float g_part2[K3_GRID * 64];           // per-block BN2 partials
__device__ float g_bn1[128];                      // scale[64], shift[64]
__device__ float g_bn2[64];                       // scale[32], shift[32]
__device__ unsigned g_cnt1 = 0;
__device__ unsigned g_cnt2 = 0;

// ---------------------------------------------------------------------------
// kSetup: cont-fold init AND the fp16 fused gather table for all 4 fields.
// ---------------------------------------------------------------------------
__global__ void __launch_bounds__(256) kSetup(
    const float* __restrict__ emb0, const float* __restrict__ emb1,
    const float* __restrict__ emb2, const float* __restrict__ emb3,
    const float* __restrict__ lin0, const float* __restrict__ lin1,
    const float* __restrict__ lin2, const float* __restrict__ lin3,
    const float* __restrict__ w1, const float* __restrict__ b1,
    const float* __restrict__ cont_w, const float* __restrict__ cont_b) {
    int bid = blockIdx.x;
    int lane = threadIdx.x & 31;
    int warp = threadIdx.x >> 5;

    if (bid == 511) {  // cont-feature fold into w1
        int j = threadIdx.x;
        if (j < 64) {
            float cb = b1[j];
            for (int c = 0; c < 8; c++) {
                float a = 0.f;
#pragma unroll
                for (int d = 0; d < 32; d++) {
                    float w = w1[j * 384 + (4 + c) * 32 + d];
                    a = fmaf(cont_w[c * 32 + d], w, a);
                    cb = fmaf(cont_b[c * 32 + d], w, cb);
                }
                g_A[j * 8 + c] = a;
            }
            g_cb[j] = cb;
        }
        return;
    }

    const float* emb;
    const float* lin;
    int V, gOff, colOff, wfirst, nwarp;
    if (bid < 506) {
        emb = emb0; lin = lin0; V = FD0; gOff = 0; colOff = 0;
        wfirst = bid * 8 + warp; nwarp = 506 * 8;
    } else if (bid < 510) {
        emb = emb1; lin = lin1; V = FD1; gOff = GOFF1; colOff = 32;
        wfirst = (bid - 506) * 8 + warp; nwarp = 32;
    } else if (warp < 4) {
        emb = emb2; lin = lin2; V = FD2; gOff = GOFF2; colOff = 64;
        wfirst = warp; nwarp = 4;
    } else {
        emb = emb3; lin = lin3; V = FD3; gOff = GOFF3; colOff = 96;
        wfirst = warp - 4; nwarp = 4;
    }

    float wa[32], wb[32];
#pragma unroll
    for (int d = 0; d < 32; d++) {
        wa[d] = w1[lane * 384 + colOff + d];
        wb[d] = w1[(lane + 32) * 384 + colOff + d];
    }
    for (int v = wfirst; v < V; v += nwarp) {
        float ev = emb[v * 32 + lane];
        float lv = lin[v * 32 + lane];
        float a0 = 0.f, a1 = 0.f;
#pragma unroll
        for (int d = 0; d < 32; d++) {
            float e = __shfl_sync(0xffffffffu, ev, d);
            a0 = fmaf(e, wa[d], a0);
            a1 = fmaf(e, wb[d], a1);
        }
        uint2 pk;
        pk.x = h2u(__floats2half2_rn(a0, a1));
        pk.y = h2u(__floats2half2_rn(lv, ev));
        g_Gh[(size_t)(gOff + v) * 32 + lane] = pk;
    }
}

// ---------------------------------------------------------------------------
// Kernel 1: contiguous 32-row chunk per warp, 2 rows per iteration,
// one LDG.64 per (feature,row) from the fp16 fused table.
// FM + linear -> out (streaming store); h1 -> fp16; BN1 partials; last
// block finalizes BN1.
// ---------------------------------------------------------------------------
__global__ void __launch_bounds__(256) k1(
    const float* __restrict__ x,
    const float* __restrict__ cont_w, const float* __restrict__ cont_b,
    const float* __restrict__ clin_w, const float* __restrict__ clin_b,
    const float* __restrict__ fin_bias,
    const float* __restrict__ g1, const float* __restrict__ beta1,
    float* __restrict__ out) {
    int lane = threadIdx.x & 31;
    int warp = threadIdx.x >> 5;
    int gw = blockIdx.x * 8 + warp;          // 6400 warps x 32 rows = NROWS
    int rbase = gw * 32;

    float cw[8], cbv[8], clw[8], clb[8], A0[8], A1[8];
#pragma unroll
    for (int c = 0; c < 8; c++) {
        cw[c] = cont_w[c * 32 + lane];
        cbv[c] = cont_b[c * 32 + lane];
        clw[c] = clin_w[c * 32 + lane];
        clb[c] = clin_b[c * 32 + lane];
        A0[c] = g_A[lane * 8 + c];
        A1[c] = g_A[(lane + 32) * 8 + c];
    }
    float finb = fin_bias[lane];
    float cb0 = g_cb[lane], cb1 = g_cb[lane + 32];
    float sum0 = 0.f, sq0 = 0.f, sum1 = 0.f, sq1 = 0.f;

    for (int it = 0; it < 16; it++) {
        int rA = rbase + it * 2;
        int rB = rA + 1;
        float xv = 0.f;
        if (lane < 24) xv = x[rA * 12 + lane];
        int iA0 = (int)__shfl_sync(0xffffffffu, xv, 0);
        int iA1 = (int)__shfl_sync(0xffffffffu, xv, 1);
        int iA2 = (int)__shfl_sync(0xffffffffu, xv, 2);
        int iA3 = (int)__shfl_sync(0xffffffffu, xv, 3);
        int iB0 = (int)__shfl_sync(0xffffffffu, xv, 12);
        int iB1 = (int)__shfl_sync(0xffffffffu, xv, 13);
        int iB2 = (int)__shfl_sync(0xffffffffu, xv, 14);
        int iB3 = (int)__shfl_sync(0xffffffffu, xv, 15);
        float xcA[8], xcB[8];
#pragma unroll
        for (int c = 0; c < 8; c++) {
            xcA[c] = __shfl_sync(0xffffffffu, xv, 4 + c);
            xcB[c] = __shfl_sync(0xffffffffu, xv, 16 + c);
        }

        // 8 independent 8B gathers (one per feature per row)
        uint2 gA0 = g_Gh[(size_t)iA0 * 32 + lane];
        uint2 gA1 = g_Gh[(size_t)(GOFF1 + iA1) * 32 + lane];
        uint2 gA2 = g_Gh[(size_t)(GOFF2 + iA2) * 32 + lane];
        uint2 gA3 = g_Gh[(size_t)(GOFF3 + iA3) * 32 + lane];
        uint2 gB0 = g_Gh[(size_t)iB0 * 32 + lane];
        uint2 gB1 = g_Gh[(size_t)(GOFF1 + iB1) * 32 + lane];
        uint2 gB2 = g_Gh[(size_t)(GOFF2 + iB2) * 32 + lane];
        uint2 gB3 = g_Gh[(size_t)(GOFF3 + iB3) * 32 + lane];

        // row A
        {
            float2 p0 = __half22float2(u2h(gA0.x)), le0 = __half22float2(u2h(gA0.y));
            float2 p1 = __half22float2(u2h(gA1.x)), le1 = __half22float2(u2h(gA1.y));
            float2 p2 = __half22float2(u2h(gA2.x)), le2 = __half22float2(u2h(gA2.y));
            float2 p3 = __half22float2(u2h(gA3.x)), le3 = __half22float2(u2h(gA3.y));
            float s = le0.y + le1.y + le2.y + le3.y;
            float sq = le0.y * le0.y + le1.y * le1.y + le2.y * le2.y + le3.y * le3.y;
            float lin = finb + le0.x + le1.x + le2.x + le3.x;
#pragma unroll
            for (int c = 0; c < 8; c++) {
                float e = fmaf(xcA[c], cw[c], cbv[c]);
                s += e;
                sq = fmaf(e, e, sq);
                lin += fmaf(xcA[c], clw[c], clb[c]);
            }
            __stwt(&out[(size_t)rA * 32 + lane], lin + 0.5f * (s * s - sq));
            float a0 = cb0 + p0.x + p1.x + p2.x + p3.x;
            float a1 = cb1 + p0.y + p1.y + p2.y + p3.y;
#pragma unroll
            for (int c = 0; c < 8; c++) {
                a0 = fmaf(xcA[c], A0[c], a0);
                a1 = fmaf(xcA[c], A1[c], a1);
            }
            g_h1h[(size_t)rA * 32 + lane] = __floats2half2_rn(a0, a1);
            sum0 += a0; sq0 = fmaf(a0, a0, sq0);
            sum1 += a1; sq1 = fmaf(a1, a1, sq1);
        }
        // row B
        {
            float2 p0 = __half22float2(u2h(gB0.x)), le0 = __half22float2(u2h(gB0.y));
            float2 p1 = __half22float2(u2h(gB1.x)), le1 = __half22float2(u2h(gB1.y));
            float2 p2 = __half22float2(u2h(gB2.x)), le2 = __half22float2(u2h(gB2.y));
            float2 p3 = __half22float2(u2h(gB3.x)), le3 = __half22float2(u2h(gB3.y));
            float s = le0.y + le1.y + le2.y + le3.y;
            float sq = le0.y * le0.y + le1.y * le1.y + le2.y * le2.y + le3.y * le3.y;
            float lin = finb + le0.x + le1.x + le2.x + le3.x;
#pragma unroll
            for (int c = 0; c < 8; c++) {
                float e = fmaf(xcB[c], cw[c], cbv[c]);
                s += e;
                sq = fmaf(e, e, sq);
                lin += fmaf(xcB[c], clw[c], clb[c]);
            }
            __stwt(&out[(size_t)rB * 32 + lane], lin + 0.5f * (s * s - sq));
            float a0 = cb0 + p0.x + p1.x + p2.x + p3.x;
            float a1 = cb1 + p0.y + p1.y + p2.y + p3.y;
#pragma unroll
            for (int c = 0; c < 8; c++) {
                a0 = fmaf(xcB[c], A0[c], a0);
                a1 = fmaf(xcB[c], A1[c], a1);
            }
            g_h1h[(size_t)rB * 32 + lane] = __floats2half2_rn(a0, a1);
            sum0 += a0; sq0 = fmaf(a0, a0, sq0);
            sum1 += a1; sq1 = fmaf(a1, a1, sq1);
        }
    }

    __shared__ float rs[64][8], rq[64][8];
    rs[lane][warp] = sum0; rs[lane + 32][warp] = sum1;
    rq[lane][warp] = sq0;  rq[lane + 32][warp] = sq1;
    __syncthreads();
    int t = threadIdx.x;
    if (t < 64) {
        float a = 0.f;
#pragma unroll
        for (int w = 0; w < 8; w++) a += rs[t][w];
        g_part1[blockIdx.x * 128 + t] = a;
    } else if (t < 128) {
        float a = 0.f;
#pragma unroll
        for (int w = 0; w < 8; w++) a += rq[t - 64][w];
        g_part1[blockIdx.x * 128 + t] = a;
    }

    __threadfence();
    __shared__ unsigned s_last;
    if (t == 0) {
        unsigned tk = atomicAdd(&g_cnt1, 1u);
        s_last = (tk == gridDim.x - 1) ? 1u : 0u;
    }
    __syncthreads();
    if (s_last) {
        __shared__ float sm[256];
        int ch = t & 127;
        int half = t >> 7;   // 2 slices of 400 blocks
        float a = 0.f;
        int b0 = half * (K1_BLOCKS / 2);
        for (int b = b0; b < b0 + K1_BLOCKS / 2; b++) a += g_part1[b * 128 + ch];
        sm[t] = a;
        __syncthreads();
        if (t < 64) {
            float s = sm[t] + sm[128 + t];
            float q = sm[64 + t] + sm[192 + t];
            float mean = s / (float)NROWS;
            float var = q / (float)NROWS - mean * mean;
            float scale = g1[t] * rsqrtf(var + BN_EPS);
            g_bn1[t] = scale;
            g_bn1[64 + t] = beta1[t] - mean * scale;
        }
        if (t == 0) g_cnt1 = 0;
    }
}

// ---------------------------------------------------------------------------
// Kernel 3: smem-tiled plain-FFMA GEMM.
// h2 = relu(bn1(h1)) @ w2^T + b2; h1 read fp16, h2 written fp16.
// Thread: 4 rows x 4 consecutive cols. BN2 partials; last block finalizes.
// ---------------------------------------------------------------------------
__global__ void __launch_bounds__(256) k3(const float* __restrict__ w2,
                                          const float* __restrict__ b2,
                                          const float* __restrict__ g2,
                                          const float* __restrict__ beta2) {
    __shared__ __align__(16) float a[TILE_R * 68];   // bn+relu(h1), stride 68
    __shared__ float wt[64 * 36];                    // w2^T: wt[k*36+j]
    __shared__ float sc[64], sh[64];
    __shared__ float wsum[8 * 32], wsq[8 * 32];

    int tid = threadIdx.x;
    int lane = tid & 31, warp = tid >> 5;
    int tr = lane >> 3, tj = lane & 7;
    int j0 = tj * 4;

    for (int i = tid; i < 2048; i += 256) {
        int j = i >> 6, k = i & 63;
        wt[k * 36 + j] = w2[i];
    }
    if (tid < 64) { sc[tid] = g_bn1[tid]; sh[tid] = g_bn1[64 + tid]; }
    float bj[4];
#pragma unroll
    for (int c = 0; c < 4; c++) bj[c] = b2[j0 + c];
    __syncthreads();

    float lsum[4] = {0.f, 0.f, 0.f, 0.f}, lsq[4] = {0.f, 0.f, 0.f, 0.f};
    int rbase = warp * 16 + tr;

    for (int tile = blockIdx.x; tile < N_TILES; tile += gridDim.x) {
        size_t base = (size_t)tile * TILE_R;
        // stage: read fp16 (c,c+32) pairs, apply bn1+relu, store fp32 smem
        for (int i = tid; i < TILE_R * 8; i += 256) {
            int r = i >> 3, c4 = (i & 7) * 4;
            uint4 raw = *(const uint4*)&g_h1h[(base + r) * 32 + c4];
            const __half2* hp = (const __half2*)&raw;
            float lo[4], hi[4];
#pragma unroll
            for (int m = 0; m < 4; m++) {
                float2 f = __half22float2(hp[m]);
                lo[m] = fmaxf(fmaf(f.x, sc[c4 + m], sh[c4 + m]), 0.f);
                hi[m] = fmaxf(fmaf(f.y, sc[c4 + m + 32], sh[c4 + m + 32]), 0.f);
            }
            *(float4*)&a[r * 68 + c4] = make_float4(lo[0], lo[1], lo[2], lo[3]);
            *(float4*)&a[r * 68 + 32 + c4] = make_float4(hi[0], hi[1], hi[2], hi[3]);
        }
        __syncthreads();

        float acc[4][4];
#pragma unroll
        for (int i = 0; i < 4; i++)
#pragma unroll
            for (int c = 0; c < 4; c++) acc[i][c] = 0.f;

#pragma unroll 4
        for (int k = 0; k < 64; k += 4) {
            float4 w0 = *(float4*)&wt[(k + 0) * 36 + j0];
            float4 w1v = *(float4*)&wt[(k + 1) * 36 + j0];
            float4 w2v = *(float4*)&wt[(k + 2) * 36 + j0];
            float4 w3 = *(float4*)&wt[(k + 3) * 36 + j0];
#pragma unroll
            for (int i = 0; i < 4; i++) {
                float4 av = *(float4*)&a[(rbase + i * 4) * 68 + k];
                acc[i][0] = fmaf(av.x, w0.x, acc[i][0]);
                acc[i][1] = fmaf(av.x, w0.y, acc[i][1]);
                acc[i][2] = fmaf(av.x, w0.z, acc[i][2]);
                acc[i][3] = fmaf(av.x, w0.w, acc[i][3]);
                acc[i][0] = fmaf(av.y, w1v.x, acc[i][0]);
                acc[i][1] = fmaf(av.y, w1v.y, acc[i][1]);
                acc[i][2] = fmaf(av.y, w1v.z, acc[i][2]);
                acc[i][3] = fmaf(av.y, w1v.w, acc[i][3]);
                acc[i][0] = fmaf(av.z, w2v.x, acc[i][0]);
                acc[i][1] = fmaf(av.z, w2v.y, acc[i][1]);
                acc[i][2] = fmaf(av.z, w2v.z, acc[i][2]);
                acc[i][3] = fmaf(av.z, w2v.w, acc[i][3]);
                acc[i][0] = fmaf(av.w, w3.x, acc[i][0]);
                acc[i][1] = fmaf(av.w, w3.y, acc[i][1]);
                acc[i][2] = fmaf(av.w, w3.z, acc[i][2]);
                acc[i][3] = fmaf(av.w, w3.w, acc[i][3]);
            }
        }

#pragma unroll
        for (int i = 0; i < 4; i++) {
            size_t r = base + rbase + i * 4;
            float v0 = acc[i][0] + bj[0];
            float v1 = acc[i][1] + bj[1];
            float v2 = acc[i][2] + bj[2];
            float v3 = acc[i][3] + bj[3];
            uint2 pk;
            pk.x = h2u(__floats2half2_rn(v0, v1));
            pk.y = h2u(__floats2half2_rn(v2, v3));
            *(uint2*)&g_h2h[r * 32 + j0] = pk;
            lsum[0] += v0; lsq[0] = fmaf(v0, v0, lsq[0]);
            lsum[1] += v1; lsq[1] = fmaf(v1, v1, lsq[1]);
            lsum[2] += v2; lsq[2] = fmaf(v2, v2, lsq[2]);
            lsum[3] += v3; lsq[3] = fmaf(v3, v3, lsq[3]);
        }
        __syncthreads();
    }

    // reduce BN2 partials over tr groups (lanes xor 8,16), then across warps
#pragma unroll
    for (int c = 0; c < 4; c++) {
        lsum[c] += __shfl_xor_sync(0xffffffffu, lsum[c], 8);
        lsum[c] += __shfl_xor_sync(0xffffffffu, lsum[c], 16);
        lsq[c] += __shfl_xor_sync(0xffffffffu, lsq[c], 8);
        lsq[c] += __shfl_xor_sync(0xffffffffu, lsq[c], 16);
    }
    if (tr == 0) {
#pragma unroll
        for (int c = 0; c < 4; c++) {
            wsum[warp * 32 + j0 + c] = lsum[c];
            wsq[warp * 32 + j0 + c] = lsq[c];
        }
    }
    __syncthreads();
    int t = tid;
    if (t < 32) {
        float s = 0.f;
#pragma unroll
        for (int w = 0; w < 8; w++) s += wsum[w * 32 + t];
        g_part2[blockIdx.x * 64 + t] = s;
    } else if (t < 64) {
        float q = 0.f;
#pragma unroll
        for (int w = 0; w < 8; w++) q += wsq[w * 32 + (t - 32)];
        g_part2[blockIdx.x * 64 + t] = q;
    }

    __threadfence();
    __shared__ unsigned s_last;
    if (t == 0) {
        unsigned tk = atomicAdd(&g_cnt2, 1u);
        s_last = (tk == gridDim.x - 1) ? 1u : 0u;
    }
    __syncthreads();
    if (s_last) {
        __shared__ float sm[256];
        int ch = t & 63;
        int sl = t >> 6;   // 4 slices of 148
        float aa = 0.f;
        int b0 = sl * (K3_GRID / 4);
        for (int b = b0; b < b0 + K3_GRID / 4; b++) aa += g_part2[b * 64 + ch];
        sm[t] = aa;
        __syncthreads();
        if (t < 32) {
            float s = (sm[t] + sm[64 + t]) + (sm[128 + t] + sm[192 + t]);
            float q = (sm[32 + t] + sm[96 + t]) + (sm[160 + t] + sm[224 + t]);
            float mean = s / (float)NROWS;
            float var = q / (float)NROWS - mean * mean;
            float scale = g2[t] * rsqrtf(var + BN_EPS);
            g_bn2[t] = scale;
            g_bn2[32 + t] = beta2[t] - mean * scale;
        }
        if (t == 0) g_cnt2 = 0;
    }
}

// ---------------------------------------------------------------------------
// Kernel 5: smem-tiled plain-FFMA GEMM, h2 read fp16.
// out += relu(bn2(h2)) @ w_out^T + b_out.
// ---------------------------------------------------------------------------
__global__ void __launch_bounds__(256) k5(const float* __restrict__ wout,
                                          const float* __restrict__ bout,
                                          float* __restrict__ out) {
    __shared__ __align__(16) float a[TILE_R * 36];   // bn+relu(h2), stride 36
    __shared__ float wt[32 * 36];                    // wout^T: wt[k*36+j]
    __shared__ float sc[32], sh[32];

    int tid = threadIdx.x;
    int lane = tid & 31, warp = tid >> 5;
    int tr = lane >> 3, tj = lane & 7;
    int j0 = tj * 4;

    for (int i = tid; i < 1024; i += 256) {
        int j = i >> 5, k = i & 31;
        wt[k * 36 + j] = wout[i];
    }
    if (tid < 32) { sc[tid] = g_bn2[tid]; sh[tid] = g_bn2[32 + tid]; }
    float bj[4];
#pragma unroll
    for (int c = 0; c < 4; c++) bj[c] = bout[j0 + c];
    __syncthreads();

    int rbase = warp * 16 + tr;

    for (int tile = blockIdx.x; tile < N_TILES; tile += gridDim.x) {
        size_t base = (size_t)tile * TILE_R;
        // stage: read 8 fp16 per uint4, apply bn2+relu, store fp32 smem
        for (int i = tid; i < TILE_R * 4; i += 256) {
            int r = i >> 2, c8 = (i & 3) * 8;
            uint4 raw = *(const uint4*)&g_h2h[(base + r) * 32 + c8];
            const __half2* hp = (const __half2*)&raw;
            float f[8];
#pragma unroll
            for (int m = 0; m < 4; m++) {
                float2 p = __half22float2(hp[m]);
                f[2 * m] = p.x;
                f[2 * m + 1] = p.y;
            }
#pragma unroll
            for (int m = 0; m < 8; m++)
                f[m] = fmaxf(fmaf(f[m], sc[c8 + m], sh[c8 + m]), 0.f);
            *(float4*)&a[r * 36 + c8] = make_float4(f[0], f[1], f[2], f[3]);
            *(float4*)&a[r * 36 + c8 + 4] = make_float4(f[4], f[5], f[6], f[7]);
        }
        __syncthreads();

        float acc[4][4];
#pragma unroll
        for (int i = 0; i < 4; i++)
#pragma unroll
            for (int c = 0; c < 4; c++) acc[i][c] = 0.f;

#pragma unroll 4
        for (int k = 0; k < 32; k += 4) {
            float4 w0 = *(float4*)&wt[(k + 0) * 36 + j0];
            float4 w1v = *(float4*)&wt[(k + 1) * 36 + j0];
            float4 w2v = *(float4*)&wt[(k + 2) * 36 + j0];
            float4 w3 = *(float4*)&wt[(k + 3) * 36 + j0];
#pragma unroll
            for (int i = 0; i < 4; i++) {
                float4 av = *(float4*)&a[(rbase + i * 4) * 36 + k];
                acc[i][0] = fmaf(av.x, w0.x, acc[i][0]);
                acc[i][1] = fmaf(av.x, w0.y, acc[i][1]);
                acc[i][2] = fmaf(av.x, w0.z, acc[i][2]);
                acc[i][3] = fmaf(av.x, w0.w, acc[i][3]);
                acc[i][0] = fmaf(av.y, w1v.x, acc[i][0]);
                acc[i][1] = fmaf(av.y, w1v.y, acc[i][1]);
                acc[i][2] = fmaf(av.y, w1v.z, acc[i][2]);
                acc[i][3] = fmaf(av.y, w1v.w, acc[i][3]);
                acc[i][0] = fmaf(av.z, w2v.x, acc[i][0]);
                acc[i][1] = fmaf(av.z, w2v.y, acc[i][1]);
                acc[i][2] = fmaf(av.z, w2v.z, acc[i][2]);
                acc[i][3] = fmaf(av.z, w2v.w, acc[i][3]);
                acc[i][0] = fmaf(av.w, w3.x, acc[i][0]);
                acc[i][1] = fmaf(av.w, w3.y, acc[i][1]);
                acc[i][2] = fmaf(av.w, w3.z, acc[i][2]);
                acc[i][3] = fmaf(av.w, w3.w, acc[i][3]);
            }
        }

#pragma unroll
        for (int i = 0; i < 4; i++) {
            size_t r = base + rbase + i * 4;
            float4 o = *(const float4*)&out[r * 32 + j0];
            o.x += acc[i][0] + bj[0];
            o.y += acc[i][1] + bj[1];
            o.z += acc[i][2] + bj[2];
            o.w += acc[i][3] + bj[3];
            *(float4*)&out[r * 32 + j0] = o;
        }
        __syncthreads();
    }
}

// ---------------------------------------------------------------------------
// Input order (setup_inputs dict insertion): x, emb0, lin0, emb1, lin1,
// emb2, lin2, emb3, lin3, cont_w, cont_b, clin_w, clin_b, fin_bias,
// w1, b1, g1, beta1, w2, b2, g2, beta2, w_out, b_out
// ---------------------------------------------------------------------------
extern "C" void kernel_launch(void* const* d_in, const int* in_sizes, int n_in,
                              void* d_out, int out_size) {
    const float* x      = (const float*)d_in[0];
    const float* emb0   = (const float*)d_in[1];
    const float* lin0   = (const float*)d_in[2];
    const float* emb1   = (const float*)d_in[3];
    const float* lin1   = (const float*)d_in[4];
    const float* emb2   = (const float*)d_in[5];
    const float* lin2   = (const float*)d_in[6];
    const float* emb3   = (const float*)d_in[7];
    const float* lin3   = (const float*)d_in[8];
    const float* cont_w = (const float*)d_in[9];
    const float* cont_b = (const float*)d_in[10];
    const float* clin_w = (const float*)d_in[11];
    const float* clin_b = (const float*)d_in[12];
    const float* fin_b  = (const float*)d_in[13];
    const float* w1     = (const float*)d_in[14];
    const float* b1     = (const float*)d_in[15];
    const float* g1     = (const float*)d_in[16];
    const float* beta1  = (const float*)d_in[17];
    const float* w2     = (const float*)d_in[18];
    const float* b2     = (const float*)d_in[19];
    const float* g2     = (const float*)d_in[20];
    const float* beta2  = (const float*)d_in[21];
    const float* w_out  = (const float*)d_in[22];
    const float* b_out  = (const float*)d_in[23];
    float* out = (float*)d_out;

    kSetup<<<SETUP_BLOCKS, 256>>>(emb0, emb1, emb2, emb3,
                                  lin0, lin1, lin2, lin3,
                                  w1, b1, cont_w, cont_b);
    k1<<<K1_BLOCKS, 256>>>(x, cont_w, cont_b, clin_w, clin_b, fin_b,
                           g1, beta1, out);
    k3<<<K3_GRID, 256>>>(w2, b2, g2, beta2);
    k5<<<K5_GRID, 256>>>(w_out, b_out, out);
}

// round 11
// speedup vs baseline: 1.2366x; 1.0148x over previous
#include <cuda_runtime.h>
#include <cuda_fp16.h>

#define NROWS 204800
#define BN_EPS 1e-5f

#define FD0 100000
#define FD1 1000
#define FD2 100
#define FD3 50
#define PV (FD0 + FD1 + FD2 + FD3)
#define GOFF1 FD0
#define GOFF2 (FD0 + FD1)
#define GOFF3 (FD0 + FD1 + FD2)

#define K1_BLOCKS 800
#define K3_GRID 592
#define K5_GRID 592
#define SETUP_BLOCKS 512
#define TILE_R 128
#define N_TILES (NROWS / TILE_R)   // 1600

__device__ __forceinline__ unsigned h2u(__half2 h) {
    return *reinterpret_cast<unsigned*>(&h);
}
__device__ __forceinline__ __half2 u2h(unsigned u) {
    return *reinterpret_cast<__half2*>(&u);
}

// Scratch (device globals; no runtime allocation allowed)
__device__ uint2 g_Gh[(size_t)PV * 32];           // fp16 fused table: (P_lo,P_hi | lin,emb)
__device__ float g_A[64 * 8];                     // cont_w folded into w1
__device__ float g_cb[64];                        // b1 + cont_b folded into w1
__device__ __half2 g_h1h[(size_t)NROWS * 32];     // h1 fp16: [r][c] = (col c, col c+32)
__device__ __half g_h2h[(size_t)NROWS * 32];      // h2 fp16 row-major
__device__ float g_part1[K1_BLOCKS * 128];        // per-block BN1 partials
__device__ float g_part2[K3_GRID * 64];           // per-block BN2 partials
__device__ float g_bn1[128];                      // scale[64], shift[64]
__device__ float g_bn2[64];                       // scale[32], shift[32]
__device__ unsigned g_cnt1 = 0;
__device__ unsigned g_cnt2 = 0;

// ---------------------------------------------------------------------------
// kSetup: cont-fold init AND the fp16 fused gather table for all 4 fields.
// ---------------------------------------------------------------------------
__global__ void __launch_bounds__(256) kSetup(
    const float* __restrict__ emb0, const float* __restrict__ emb1,
    const float* __restrict__ emb2, const float* __restrict__ emb3,
    const float* __restrict__ lin0, const float* __restrict__ lin1,
    const float* __restrict__ lin2, const float* __restrict__ lin3,
    const float* __restrict__ w1, const float* __restrict__ b1,
    const float* __restrict__ cont_w, const float* __restrict__ cont_b) {
    int bid = blockIdx.x;
    int lane = threadIdx.x & 31;
    int warp = threadIdx.x >> 5;

    if (bid == 511) {  // cont-feature fold into w1
        int j = threadIdx.x;
        if (j < 64) {
            float cb = b1[j];
            for (int c = 0; c < 8; c++) {
                float a = 0.f;
#pragma unroll
                for (int d = 0; d < 32; d++) {
                    float w = w1[j * 384 + (4 + c) * 32 + d];
                    a = fmaf(cont_w[c * 32 + d], w, a);
                    cb = fmaf(cont_b[c * 32 + d], w, cb);
                }
                g_A[j * 8 + c] = a;
            }
            g_cb[j] = cb;
        }
        return;
    }

    const float* emb;
    const float* lin;
    int V, gOff, colOff, wfirst, nwarp;
    if (bid < 506) {
        emb = emb0; lin = lin0; V = FD0; gOff = 0; colOff = 0;
        wfirst = bid * 8 + warp; nwarp = 506 * 8;
    } else if (bid < 510) {
        emb = emb1; lin = lin1; V = FD1; gOff = GOFF1; colOff = 32;
        wfirst = (bid - 506) * 8 + warp; nwarp = 32;
    } else if (warp < 4) {
        emb = emb2; lin = lin2; V = FD2; gOff = GOFF2; colOff = 64;
        wfirst = warp; nwarp = 4;
    } else {
        emb = emb3; lin = lin3; V = FD3; gOff = GOFF3; colOff = 96;
        wfirst = warp - 4; nwarp = 4;
    }

    float wa[32], wb[32];
#pragma unroll
    for (int d = 0; d < 32; d++) {
        wa[d] = w1[lane * 384 + colOff + d];
        wb[d] = w1[(lane + 32) * 384 + colOff + d];
    }
    for (int v = wfirst; v < V; v += nwarp) {
        float ev = emb[v * 32 + lane];
        float lv = lin[v * 32 + lane];
        float a0 = 0.f, a1 = 0.f;
#pragma unroll
        for (int d = 0; d < 32; d++) {
            float e = __shfl_sync(0xffffffffu, ev, d);
            a0 = fmaf(e, wa[d], a0);
            a1 = fmaf(e, wb[d], a1);
        }
        uint2 pk;
        pk.x = h2u(__floats2half2_rn(a0, a1));
        pk.y = h2u(__floats2half2_rn(lv, ev));
        g_Gh[(size_t)(gOff + v) * 32 + lane] = pk;
    }
}

// ---------------------------------------------------------------------------
// Kernel 1: contiguous 32-row chunk per warp, 4 rows per iteration,
// 16 independent LDG.64 gathers in flight. FM + linear -> out (streaming);
// h1 -> fp16; BN1 partials; last block finalizes BN1.
// ---------------------------------------------------------------------------
__global__ void __launch_bounds__(256) k1(
    const float* __restrict__ x,
    const float* __restrict__ cont_w, const float* __restrict__ cont_b,
    const float* __restrict__ clin_w, const float* __restrict__ clin_b,
    const float* __restrict__ fin_bias,
    const float* __restrict__ g1, const float* __restrict__ beta1,
    float* __restrict__ out) {
    int lane = threadIdx.x & 31;
    int warp = threadIdx.x >> 5;
    int gw = blockIdx.x * 8 + warp;          // 6400 warps x 32 rows = NROWS
    int rbase = gw * 32;
    const unsigned FULL = 0xffffffffu;

    float cw[8], cbv[8], clw[8], A0[8], A1[8];
    float finb = fin_bias[lane];
#pragma unroll
    for (int c = 0; c < 8; c++) {
        cw[c] = cont_w[c * 32 + lane];
        cbv[c] = cont_b[c * 32 + lane];
        clw[c] = clin_w[c * 32 + lane];
        finb += clin_b[c * 32 + lane];       // fold sum of clin_b into bias
        A0[c] = g_A[lane * 8 + c];
        A1[c] = g_A[(lane + 32) * 8 + c];
    }
    float cb0 = g_cb[lane], cb1 = g_cb[lane + 32];
    float sum0 = 0.f, sq0 = 0.f, sum1 = 0.f, sq1 = 0.f;

    for (int it = 0; it < 8; it++) {
        int r0 = rbase + it * 4;
        // 48 x-floats (4 rows x 12) via one float2 per lane (lanes 0..23)
        float2 xv2 = make_float2(0.f, 0.f);
        if (lane < 24) xv2 = ((const float2*)(x + (size_t)r0 * 12))[lane];

        // extract 16 indices (element e of the 48: lane e/2, component e&1)
        int idx[4][4];
#pragma unroll
        for (int m = 0; m < 4; m++) {
#pragma unroll
            for (int f = 0; f < 4; f++) {
                int e = m * 12 + f;
                float xe = (e & 1) ? __shfl_sync(FULL, xv2.y, e >> 1)
                                   : __shfl_sync(FULL, xv2.x, e >> 1);
                idx[m][f] = (int)xe;
            }
        }

        // 16 independent 8B gathers, all in flight
        uint2 g[4][4];
#pragma unroll
        for (int m = 0; m < 4; m++) {
            g[m][0] = g_Gh[(size_t)idx[m][0] * 32 + lane];
            g[m][1] = g_Gh[(size_t)(GOFF1 + idx[m][1]) * 32 + lane];
            g[m][2] = g_Gh[(size_t)(GOFF2 + idx[m][2]) * 32 + lane];
            g[m][3] = g_Gh[(size_t)(GOFF3 + idx[m][3]) * 32 + lane];
        }

#pragma unroll
        for (int m = 0; m < 4; m++) {
            int r = r0 + m;
            float xc[8];
#pragma unroll
            for (int c = 0; c < 8; c++) {
                int e = m * 12 + 4 + c;
                xc[c] = (e & 1) ? __shfl_sync(FULL, xv2.y, e >> 1)
                                : __shfl_sync(FULL, xv2.x, e >> 1);
            }
            float2 p0 = __half22float2(u2h(g[m][0].x)), le0 = __half22float2(u2h(g[m][0].y));
            float2 p1 = __half22float2(u2h(g[m][1].x)), le1 = __half22float2(u2h(g[m][1].y));
            float2 p2 = __half22float2(u2h(g[m][2].x)), le2 = __half22float2(u2h(g[m][2].y));
            float2 p3 = __half22float2(u2h(g[m][3].x)), le3 = __half22float2(u2h(g[m][3].y));

            float s = le0.y + le1.y + le2.y + le3.y;
            float sq = le0.y * le0.y + le1.y * le1.y + le2.y * le2.y + le3.y * le3.y;
            float lin = finb + le0.x + le1.x + le2.x + le3.x;
#pragma unroll
            for (int c = 0; c < 8; c++) {
                float e = fmaf(xc[c], cw[c], cbv[c]);
                s += e;
                sq = fmaf(e, e, sq);
                lin = fmaf(xc[c], clw[c], lin);
            }
            __stwt(&out[(size_t)r * 32 + lane], lin + 0.5f * (s * s - sq));

            float a0 = cb0 + p0.x + p1.x + p2.x + p3.x;
            float a1 = cb1 + p0.y + p1.y + p2.y + p3.y;
#pragma unroll
            for (int c = 0; c < 8; c++) {
                a0 = fmaf(xc[c], A0[c], a0);
                a1 = fmaf(xc[c], A1[c], a1);
            }
            g_h1h[(size_t)r * 32 + lane] = __floats2half2_rn(a0, a1);
            sum0 += a0; sq0 = fmaf(a0, a0, sq0);
            sum1 += a1; sq1 = fmaf(a1, a1, sq1);
        }
    }

    __shared__ float rs[64][8], rq[64][8];
    rs[lane][warp] = sum0; rs[lane + 32][warp] = sum1;
    rq[lane][warp] = sq0;  rq[lane + 32][warp] = sq1;
    __syncthreads();
    int t = threadIdx.x;
    if (t < 64) {
        float a = 0.f;
#pragma unroll
        for (int w = 0; w < 8; w++) a += rs[t][w];
        g_part1[blockIdx.x * 128 + t] = a;
    } else if (t < 128) {
        float a = 0.f;
#pragma unroll
        for (int w = 0; w < 8; w++) a += rq[t - 64][w];
        g_part1[blockIdx.x * 128 + t] = a;
    }

    __threadfence();
    __shared__ unsigned s_last;
    if (t == 0) {
        unsigned tk = atomicAdd(&g_cnt1, 1u);
        s_last = (tk == gridDim.x - 1) ? 1u : 0u;
    }
    __syncthreads();
    if (s_last) {
        __shared__ float sm[256];
        int ch = t & 127;
        int half = t >> 7;   // 2 slices of 400 blocks
        float a = 0.f;
        int b0 = half * (K1_BLOCKS / 2);
        for (int b = b0; b < b0 + K1_BLOCKS / 2; b++) a += g_part1[b * 128 + ch];
        sm[t] = a;
        __syncthreads();
        if (t < 64) {
            float s = sm[t] + sm[128 + t];
            float q = sm[64 + t] + sm[192 + t];
            float mean = s / (float)NROWS;
            float var = q / (float)NROWS - mean * mean;
            float scale = g1[t] * rsqrtf(var + BN_EPS);
            g_bn1[t] = scale;
            g_bn1[64 + t] = beta1[t] - mean * scale;
        }
        if (t == 0) g_cnt1 = 0;
    }
}

// ---------------------------------------------------------------------------
// Kernel 3: smem-tiled plain-FFMA GEMM.
// h2 = relu(bn1(h1)) @ w2^T + b2; h1 read fp16, h2 written fp16.
// Thread: 4 rows x 4 consecutive cols. BN2 partials; last block finalizes.
// ---------------------------------------------------------------------------
__global__ void __launch_bounds__(256) k3(const float* __restrict__ w2,
                                          const float* __restrict__ b2,
                                          const float* __restrict__ g2,
                                          const float* __restrict__ beta2) {
    __shared__ __align__(16) float a[TILE_R * 68];   // bn+relu(h1), stride 68
    __shared__ float wt[64 * 36];                    // w2^T: wt[k*36+j]
    __shared__ float sc[64], sh[64];
    __shared__ float wsum[8 * 32], wsq[8 * 32];

    int tid = threadIdx.x;
    int lane = tid & 31, warp = tid >> 5;
    int tr = lane >> 3, tj = lane & 7;
    int j0 = tj * 4;

    for (int i = tid; i < 2048; i += 256) {
        int j = i >> 6, k = i & 63;
        wt[k * 36 + j] = w2[i];
    }
    if (tid < 64) { sc[tid] = g_bn1[tid]; sh[tid] = g_bn1[64 + tid]; }
    float bj[4];
#pragma unroll
    for (int c = 0; c < 4; c++) bj[c] = b2[j0 + c];
    __syncthreads();

    float lsum[4] = {0.f, 0.f, 0.f, 0.f}, lsq[4] = {0.f, 0.f, 0.f, 0.f};
    int rbase = warp * 16 + tr;

    for (int tile = blockIdx.x; tile < N_TILES; tile += gridDim.x) {
        size_t base = (size_t)tile * TILE_R;
        // stage: read fp16 (c,c+32) pairs, apply bn1+relu, store fp32 smem
        for (int i = tid; i < TILE_R * 8; i += 256) {
            int r = i >> 3, c4 = (i & 7) * 4;
            uint4 raw = *(const uint4*)&g_h1h[(base + r) * 32 + c4];
            const __half2* hp = (const __half2*)&raw;
            float lo[4], hi[4];
#pragma unroll
            for (int m = 0; m < 4; m++) {
                float2 f = __half22float2(hp[m]);
                lo[m] = fmaxf(fmaf(f.x, sc[c4 + m], sh[c4 + m]), 0.f);
                hi[m] = fmaxf(fmaf(f.y, sc[c4 + m + 32], sh[c4 + m + 32]), 0.f);
            }
            *(float4*)&a[r * 68 + c4] = make_float4(lo[0], lo[1], lo[2], lo[3]);
            *(float4*)&a[r * 68 + 32 + c4] = make_float4(hi[0], hi[1], hi[2], hi[3]);
        }
        __syncthreads();

        float acc[4][4];
#pragma unroll
        for (int i = 0; i < 4; i++)
#pragma unroll
            for (int c = 0; c < 4; c++) acc[i][c] = 0.f;

#pragma unroll 4
        for (int k = 0; k < 64; k += 4) {
            float4 w0 = *(float4*)&wt[(k + 0) * 36 + j0];
            float4 w1v = *(float4*)&wt[(k + 1) * 36 + j0];
            float4 w2v = *(float4*)&wt[(k + 2) * 36 + j0];
            float4 w3 = *(float4*)&wt[(k + 3) * 36 + j0];
#pragma unroll
            for (int i = 0; i < 4; i++) {
                float4 av = *(float4*)&a[(rbase + i * 4) * 68 + k];
                acc[i][0] = fmaf(av.x, w0.x, acc[i][0]);
                acc[i][1] = fmaf(av.x, w0.y, acc[i][1]);
                acc[i][2] = fmaf(av.x, w0.z, acc[i][2]);
                acc[i][3] = fmaf(av.x, w0.w, acc[i][3]);
                acc[i][0] = fmaf(av.y, w1v.x, acc[i][0]);
                acc[i][1] = fmaf(av.y, w1v.y, acc[i][1]);
                acc[i][2] = fmaf(av.y, w1v.z, acc[i][2]);
                acc[i][3] = fmaf(av.y, w1v.w, acc[i][3]);
                acc[i][0] = fmaf(av.z, w2v.x, acc[i][0]);
                acc[i][1] = fmaf(av.z, w2v.y, acc[i][1]);
                acc[i][2] = fmaf(av.z, w2v.z, acc[i][2]);
                acc[i][3] = fmaf(av.z, w2v.w, acc[i][3]);
                acc[i][0] = fmaf(av.w, w3.x, acc[i][0]);
                acc[i][1] = fmaf(av.w, w3.y, acc[i][1]);
                acc[i][2] = fmaf(av.w, w3.z, acc[i][2]);
                acc[i][3] = fmaf(av.w, w3.w, acc[i][3]);
            }
        }

#pragma unroll
        for (int i = 0; i < 4; i++) {
            size_t r = base + rbase + i * 4;
            float v0 = acc[i][0] + bj[0];
            float v1 = acc[i][1] + bj[1];
            float v2 = acc[i][2] + bj[2];
            float v3 = acc[i][3] + bj[3];
            uint2 pk;
            pk.x = h2u(__floats2half2_rn(v0, v1));
            pk.y = h2u(__floats2half2_rn(v2, v3));
            *(uint2*)&g_h2h[r * 32 + j0] = pk;
            lsum[0] += v0; lsq[0] = fmaf(v0, v0, lsq[0]);
            lsum[1] += v1; lsq[1] = fmaf(v1, v1, lsq[1]);
            lsum[2] += v2; lsq[2] = fmaf(v2, v2, lsq[2]);
            lsum[3] += v3; lsq[3] = fmaf(v3, v3, lsq[3]);
        }
        __syncthreads();
    }

    // reduce BN2 partials over tr groups (lanes xor 8,16), then across warps
#pragma unroll
    for (int c = 0; c < 4; c++) {
        lsum[c] += __shfl_xor_sync(0xffffffffu, lsum[c], 8);
        lsum[c] += __shfl_xor_sync(0xffffffffu, lsum[c], 16);
        lsq[c] += __shfl_xor_sync(0xffffffffu, lsq[c], 8);
        lsq[c] += __shfl_xor_sync(0xffffffffu, lsq[c], 16);
    }
    if (tr == 0) {
#pragma unroll
        for (int c = 0; c < 4; c++) {
            wsum[warp * 32 + j0 + c] = lsum[c];
            wsq[warp * 32 + j0 + c] = lsq[c];
        }
    }
    __syncthreads();
    int t = tid;
    if (t < 32) {
        float s = 0.f;
#pragma unroll
        for (int w = 0; w < 8; w++) s += wsum[w * 32 + t];
        g_part2[blockIdx.x * 64 + t] = s;
    } else if (t < 64) {
        float q = 0.f;
#pragma unroll
        for (int w = 0; w < 8; w++) q += wsq[w * 32 + (t - 32)];
        g_part2[blockIdx.x * 64 + t] = q;
    }

    __threadfence();
    __shared__ unsigned s_last;
    if (t == 0) {
        unsigned tk = atomicAdd(&g_cnt2, 1u);
        s_last = (tk == gridDim.x - 1) ? 1u : 0u;
    }
    __syncthreads();
    if (s_last) {
        __shared__ float sm[256];
        int ch = t & 63;
        int sl = t >> 6;   // 4 slices of 148
        float aa = 0.f;
        int b0 = sl * (K3_GRID / 4);
        for (int b = b0; b < b0 + K3_GRID / 4; b++) aa += g_part2[b * 64 + ch];
        sm[t] = aa;
        __syncthreads();
        if (t < 32) {
            float s = (sm[t] + sm[64 + t]) + (sm[128 + t] + sm[192 + t]);
            float q = (sm[32 + t] + sm[96 + t]) + (sm[160 + t] + sm[224 + t]);
            float mean = s / (float)NROWS;
            float var = q / (float)NROWS - mean * mean;
            float scale = g2[t] * rsqrtf(var + BN_EPS);
            g_bn2[t] = scale;
            g_bn2[32 + t] = beta2[t] - mean * scale;
        }
        if (t == 0) g_cnt2 = 0;
    }
}

// ---------------------------------------------------------------------------
// Kernel 5: smem-tiled plain-FFMA GEMM, h2 read fp16.
// out += relu(bn2(h2)) @ w_out^T + b_out.
// ---------------------------------------------------------------------------
__global__ void __launch_bounds__(256) k5(const float* __restrict__ wout,
                                          const float* __restrict__ bout,
                                          float* __restrict__ out) {
    __shared__ __align__(16) float a[TILE_R * 36];   // bn+relu(h2), stride 36
    __shared__ float wt[32 * 36];                    // wout^T: wt[k*36+j]
    __shared__ float sc[32], sh[32];

    int tid = threadIdx.x;
    int lane = tid & 31, warp = tid >> 5;
    int tr = lane >> 3, tj = lane & 7;
    int j0 = tj * 4;

    for (int i = tid; i < 1024; i += 256) {
        int j = i >> 5, k = i & 31;
        wt[k * 36 + j] = wout[i];
    }
    if (tid < 32) { sc[tid] = g_bn2[tid]; sh[tid] = g_bn2[32 + tid]; }
    float bj[4];
#pragma unroll
    for (int c = 0; c < 4; c++) bj[c] = bout[j0 + c];
    __syncthreads();

    int rbase = warp * 16 + tr;

    for (int tile = blockIdx.x; tile < N_TILES; tile += gridDim.x) {
        size_t base = (size_t)tile * TILE_R;
        // stage: read 8 fp16 per uint4, apply bn2+relu, store fp32 smem
        for (int i = tid; i < TILE_R * 4; i += 256) {
            int r = i >> 2, c8 = (i & 3) * 8;
            uint4 raw = *(const uint4*)&g_h2h[(base + r) * 32 + c8];
            const __half2* hp = (const __half2*)&raw;
            float f[8];
#pragma unroll
            for (int m = 0; m < 4; m++) {
                float2 p = __half22float2(hp[m]);
                f[2 * m] = p.x;
                f[2 * m + 1] = p.y;
            }
#pragma unroll
            for (int m = 0; m < 8; m++)
                f[m] = fmaxf(fmaf(f[m], sc[c8 + m], sh[c8 + m]), 0.f);
            *(float4*)&a[r * 36 + c8] = make_float4(f[0], f[1], f[2], f[3]);
            *(float4*)&a[r * 36 + c8 + 4] = make_float4(f[4], f[5], f[6], f[7]);
        }
        __syncthreads();

        float acc[4][4];
#pragma unroll
        for (int i = 0; i < 4; i++)
#pragma unroll
            for (int c = 0; c < 4; c++) acc[i][c] = 0.f;

#pragma unroll 4
        for (int k = 0; k < 32; k += 4) {
            float4 w0 = *(float4*)&wt[(k + 0) * 36 + j0];
            float4 w1v = *(float4*)&wt[(k + 1) * 36 + j0];
            float4 w2v = *(float4*)&wt[(k + 2) * 36 + j0];
            float4 w3 = *(float4*)&wt[(k + 3) * 36 + j0];
#pragma unroll
            for (int i = 0; i < 4; i++) {
                float4 av = *(float4*)&a[(rbase + i * 4) * 36 + k];
                acc[i][0] = fmaf(av.x, w0.x, acc[i][0]);
                acc[i][1] = fmaf(av.x, w0.y, acc[i][1]);
                acc[i][2] = fmaf(av.x, w0.z, acc[i][2]);
                acc[i][3] = fmaf(av.x, w0.w, acc[i][3]);
                acc[i][0] = fmaf(av.y, w1v.x, acc[i][0]);
                acc[i][1] = fmaf(av.y, w1v.y, acc[i][1]);
                acc[i][2] = fmaf(av.y, w1v.z, acc[i][2]);
                acc[i][3] = fmaf(av.y, w1v.w, acc[i][3]);
                acc[i][0] = fmaf(av.z, w2v.x, acc[i][0]);
                acc[i][1] = fmaf(av.z, w2v.y, acc[i][1]);
                acc[i][2] = fmaf(av.z, w2v.z, acc[i][2]);
                acc[i][3] = fmaf(av.z, w2v.w, acc[i][3]);
                acc[i][0] = fmaf(av.w, w3.x, acc[i][0]);
                acc[i][1] = fmaf(av.w, w3.y, acc[i][1]);
                acc[i][2] = fmaf(av.w, w3.z, acc[i][2]);
                acc[i][3] = fmaf(av.w, w3.w, acc[i][3]);
            }
        }

#pragma unroll
        for (int i = 0; i < 4; i++) {
            size_t r = base + rbase + i * 4;
            float4 o = *(const float4*)&out[r * 32 + j0];
            o.x += acc[i][0] + bj[0];
            o.y += acc[i][1] + bj[1];
            o.z += acc[i][2] + bj[2];
            o.w += acc[i][3] + bj[3];
            *(float4*)&out[r * 32 + j0] = o;
        }
        __syncthreads();
    }
}

// ---------------------------------------------------------------------------
// Input order (setup_inputs dict insertion): x, emb0, lin0, emb1, lin1,
// emb2, lin2, emb3, lin3, cont_w, cont_b, clin_w, clin_b, fin_bias,
// w1, b1, g1, beta1, w2, b2, g2, beta2, w_out, b_out
// ---------------------------------------------------------------------------
extern "C" void kernel_launch(void* const* d_in, const int* in_sizes, int n_in,
                              void* d_out, int out_size) {
    const float* x      = (const float*)d_in[0];
    const float* emb0   = (const float*)d_in[1];
    const float* lin0   = (const float*)d_in[2];
    const float* emb1   = (const float*)d_in[3];
    const float* lin1   = (const float*)d_in[4];
    const float* emb2   = (const float*)d_in[5];
    const float* lin2   = (const float*)d_in[6];
    const float* emb3   = (const float*)d_in[7];
    const float* lin3   = (const float*)d_in[8];
    const float* cont_w = (const float*)d_in[9];
    const float* cont_b = (const float*)d_in[10];
    const float* clin_w = (const float*)d_in[11];
    const float* clin_b = (const float*)d_in[12];
    const float* fin_b  = (const float*)d_in[13];
    const float* w1     = (const float*)d_in[14];
    const float* b1     = (const float*)d_in[15];
    const float* g1     = (const float*)d_in[16];
    const float* beta1  = (const float*)d_in[17];
    const float* w2     = (const float*)d_in[18];
    const float* b2     = (const float*)d_in[19];
    const float* g2     = (const float*)d_in[20];
    const float* beta2  = (const float*)d_in[21];
    const float* w_out  = (const float*)d_in[22];
    const float* b_out  = (const float*)d_in[23];
    float* out = (float*)d_out;

    kSetup<<<SETUP_BLOCKS, 256>>>(emb0, emb1, emb2, emb3,
                                  lin0, lin1, lin2, lin3,
                                  w1, b1, cont_w, cont_b);
    k1<<<K1_BLOCKS, 256>>>(x, cont_w, cont_b, clin_w, clin_b, fin_b,
                           g1, beta1, out);
    k3<<<K3_GRID, 256>>>(w2, b2, g2, beta2);
    k5<<<K5_GRID, 256>>>(w_out, b_out, out);
}

// round 12
// speedup vs baseline: 1.2617x; 1.0203x over previous
#include <cuda_runtime.h>
#include <cuda_fp16.h>

#define NROWS 204800
#define BN_EPS 1e-5f

#define FD0 100000
#define FD1 1000
#define FD2 100
#define FD3 50
#define PV (FD0 + FD1 + FD2 + FD3)
#define GOFF1 FD0
#define GOFF2 (FD0 + FD1)
#define GOFF3 (FD0 + FD1 + FD2)

#define GRID 444
#define NWARPS (GRID * 8)            // 3552
#define TILE_R 128
#define N_TILES (NROWS / TILE_R)     // 1600
#define NPAIR (NROWS / 2)            // 102400

__device__ __forceinline__ unsigned h2u(__half2 h) {
    return *reinterpret_cast<unsigned*>(&h);
}
__device__ __forceinline__ __half2 u2h(unsigned u) {
    return *reinterpret_cast<__half2*>(&u);
}

// Scratch (device globals; no runtime allocation allowed)
__device__ uint2 g_Gh[(size_t)PV * 32];          // fp16 fused table (P_lo,P_hi | lin,emb)
__device__ float g_A[64 * 8];
__device__ float g_cb[64];
__device__ __half2 g_h1h[(size_t)NROWS * 32];    // h1 fp16: (col c, col c+32)
__device__ __half g_h2h[(size_t)NROWS * 32];     // h2 fp16 row-major
__device__ float g_part1[GRID * 128];
__device__ float g_part2[GRID * 64];
__device__ float g_bn1[128];
__device__ float g_bn2[64];
// Monotonic grid-barrier counters (never reset -> graph-replay safe)
__device__ unsigned g_barA[3];
__device__ unsigned g_barR[3];

// Shared-memory union across phases
struct S1 { float rs[64][8]; float rq[64][8]; };
struct S3 { float a[TILE_R * 68]; float wt[64 * 36]; float sc[64]; float sh[64];
            float wsum[256]; float wsq[256]; };
struct S5 { float a[TILE_R * 36]; float wt[32 * 36]; float sc[32]; float sh[32]; };
union __align__(16) USh { S1 s1; S3 s3; S5 s5; float fin[256]; };

// ---------------------------------------------------------------------------
// Fused persistent kernel: setup -> bar0 -> k1 -> bar1(+BN1) -> k3 ->
// bar2(+BN2) -> k5. Barriers: monotonic arrive/release, last block finalizes.
// ---------------------------------------------------------------------------
__global__ void __launch_bounds__(256, 3) kFused(
    const float* __restrict__ x,
    const float* __restrict__ emb0, const float* __restrict__ lin0,
    const float* __restrict__ emb1, const float* __restrict__ lin1,
    const float* __restrict__ emb2, const float* __restrict__ lin2,
    const float* __restrict__ emb3, const float* __restrict__ lin3,
    const float* __restrict__ cont_w, const float* __restrict__ cont_b,
    const float* __restrict__ clin_w, const float* __restrict__ clin_b,
    const float* __restrict__ fin_bias,
    const float* __restrict__ w1, const float* __restrict__ b1,
    const float* __restrict__ g1, const float* __restrict__ beta1,
    const float* __restrict__ w2, const float* __restrict__ b2,
    const float* __restrict__ g2, const float* __restrict__ beta2,
    const float* __restrict__ wout, const float* __restrict__ bout,
    float* __restrict__ out) {
    __shared__ USh u;
    __shared__ unsigned s_tgt;
    __shared__ int s_last;

    const unsigned FULL = 0xffffffffu;
    int tid = threadIdx.x;
    int lane = tid & 31, warp = tid >> 5;
    int bid = blockIdx.x;
    int gw = bid * 8 + warp;
    const unsigned GRIDu = (unsigned)gridDim.x;

    // ===== Phase 0: build fp16 fused gather table + cont-fold =====
    {
        const float* emb = 0; const float* lin = 0;
        int V = 0, gOff = 0, colOff = 0, wfirst = 0, nwarp = 1;
        bool table = true;
        if (gw < 3472)      { emb = emb0; lin = lin0; V = FD0; gOff = 0;     colOff = 0;  wfirst = gw;        nwarp = 3472; }
        else if (gw < 3536) { emb = emb1; lin = lin1; V = FD1; gOff = GOFF1; colOff = 32; wfirst = gw - 3472; nwarp = 64; }
        else if (gw < 3540) { emb = emb2; lin = lin2; V = FD2; gOff = GOFF2; colOff = 64; wfirst = gw - 3536; nwarp = 4; }
        else if (gw < 3544) { emb = emb3; lin = lin3; V = FD3; gOff = GOFF3; colOff = 96; wfirst = gw - 3540; nwarp = 4; }
        else table = false;

        if (table) {
            float wa[32], wb[32];
#pragma unroll
            for (int d = 0; d < 32; d++) {
                wa[d] = w1[lane * 384 + colOff + d];
                wb[d] = w1[(lane + 32) * 384 + colOff + d];
            }
            for (int v = wfirst; v < V; v += nwarp) {
                float ev = emb[v * 32 + lane];
                float lv = lin[v * 32 + lane];
                float a0 = 0.f, a1 = 0.f;
#pragma unroll
                for (int d = 0; d < 32; d++) {
                    float e = __shfl_sync(FULL, ev, d);
                    a0 = fmaf(e, wa[d], a0);
                    a1 = fmaf(e, wb[d], a1);
                }
                uint2 pk;
                pk.x = h2u(__floats2half2_rn(a0, a1));
                pk.y = h2u(__floats2half2_rn(lv, ev));
                g_Gh[(size_t)(gOff + v) * 32 + lane] = pk;
            }
        } else if (tid < 64) {
            // block 443: cont-fold into w1
            int j = tid;
            float cb = b1[j];
            for (int c = 0; c < 8; c++) {
                float a = 0.f;
#pragma unroll
                for (int d = 0; d < 32; d++) {
                    float w = w1[j * 384 + (4 + c) * 32 + d];
                    a = fmaf(cont_w[c * 32 + d], w, a);
                    cb = fmaf(cont_b[c * 32 + d], w, cb);
                }
                g_A[j * 8 + c] = a;
            }
            g_cb[j] = cb;
        }
    }

    // ---- barrier 0 (no finalize) ----
    __syncthreads();
    if (tid == 0) {
        __threadfence();
        unsigned tk = atomicAdd(&g_barA[0], 1u);
        s_tgt = (tk / GRIDu + 1u) * GRIDu;
        s_last = (tk % GRIDu == GRIDu - 1u) ? 1 : 0;
    }
    __syncthreads();
    if (s_last) {
        if (tid == 0) { __threadfence(); atomicAdd(&g_barR[0], GRIDu); }
    } else if (tid == 0) {
        while (atomicAdd(&g_barR[0], 0u) < s_tgt) __nanosleep(64);
        __threadfence();
    }
    __syncthreads();

    // ===== Phase 1: FM + linear + h1 (2 rows / warp-iter) =====
    {
        float cw[8], cbv[8], clw[8], A0[8], A1[8];
        float finb = fin_bias[lane];
#pragma unroll
        for (int c = 0; c < 8; c++) {
            cw[c] = cont_w[c * 32 + lane];
            cbv[c] = cont_b[c * 32 + lane];
            clw[c] = clin_w[c * 32 + lane];
            finb += clin_b[c * 32 + lane];
            A0[c] = g_A[lane * 8 + c];
            A1[c] = g_A[(lane + 32) * 8 + c];
        }
        float cb0 = g_cb[lane], cb1 = g_cb[lane + 32];
        float sum0 = 0.f, sq0 = 0.f, sum1 = 0.f, sq1 = 0.f;

        for (int pr = gw; pr < NPAIR; pr += NWARPS) {
            int rA = pr * 2;
            int rB = rA + 1;
            float xv = 0.f;
            if (lane < 24) xv = x[(size_t)rA * 12 + lane];
            int iA0 = (int)__shfl_sync(FULL, xv, 0);
            int iA1 = (int)__shfl_sync(FULL, xv, 1);
            int iA2 = (int)__shfl_sync(FULL, xv, 2);
            int iA3 = (int)__shfl_sync(FULL, xv, 3);
            int iB0 = (int)__shfl_sync(FULL, xv, 12);
            int iB1 = (int)__shfl_sync(FULL, xv, 13);
            int iB2 = (int)__shfl_sync(FULL, xv, 14);
            int iB3 = (int)__shfl_sync(FULL, xv, 15);
            float xcA[8], xcB[8];
#pragma unroll
            for (int c = 0; c < 8; c++) {
                xcA[c] = __shfl_sync(FULL, xv, 4 + c);
                xcB[c] = __shfl_sync(FULL, xv, 16 + c);
            }

            uint2 gA0 = g_Gh[(size_t)iA0 * 32 + lane];
            uint2 gA1 = g_Gh[(size_t)(GOFF1 + iA1) * 32 + lane];
            uint2 gA2 = g_Gh[(size_t)(GOFF2 + iA2) * 32 + lane];
            uint2 gA3 = g_Gh[(size_t)(GOFF3 + iA3) * 32 + lane];
            uint2 gB0 = g_Gh[(size_t)iB0 * 32 + lane];
            uint2 gB1 = g_Gh[(size_t)(GOFF1 + iB1) * 32 + lane];
            uint2 gB2 = g_Gh[(size_t)(GOFF2 + iB2) * 32 + lane];
            uint2 gB3 = g_Gh[(size_t)(GOFF3 + iB3) * 32 + lane];

            // row A
            {
                float2 p0 = __half22float2(u2h(gA0.x)), le0 = __half22float2(u2h(gA0.y));
                float2 p1 = __half22float2(u2h(gA1.x)), le1 = __half22float2(u2h(gA1.y));
                float2 p2 = __half22float2(u2h(gA2.x)), le2 = __half22float2(u2h(gA2.y));
                float2 p3 = __half22float2(u2h(gA3.x)), le3 = __half22float2(u2h(gA3.y));
                float s = le0.y + le1.y + le2.y + le3.y;
                float sq = le0.y * le0.y + le1.y * le1.y + le2.y * le2.y + le3.y * le3.y;
                float lin = finb + le0.x + le1.x + le2.x + le3.x;
#pragma unroll
                for (int c = 0; c < 8; c++) {
                    float e = fmaf(xcA[c], cw[c], cbv[c]);
                    s += e;
                    sq = fmaf(e, e, sq);
                    lin = fmaf(xcA[c], clw[c], lin);
                }
                out[(size_t)rA * 32 + lane] = lin + 0.5f * (s * s - sq);
                float a0 = cb0 + p0.x + p1.x + p2.x + p3.x;
                float a1 = cb1 + p0.y + p1.y + p2.y + p3.y;
#pragma unroll
                for (int c = 0; c < 8; c++) {
                    a0 = fmaf(xcA[c], A0[c], a0);
                    a1 = fmaf(xcA[c], A1[c], a1);
                }
                g_h1h[(size_t)rA * 32 + lane] = __floats2half2_rn(a0, a1);
                sum0 += a0; sq0 = fmaf(a0, a0, sq0);
                sum1 += a1; sq1 = fmaf(a1, a1, sq1);
            }
            // row B
            {
                float2 p0 = __half22float2(u2h(gB0.x)), le0 = __half22float2(u2h(gB0.y));
                float2 p1 = __half22float2(u2h(gB1.x)), le1 = __half22float2(u2h(gB1.y));
                float2 p2 = __half22float2(u2h(gB2.x)), le2 = __half22float2(u2h(gB2.y));
                float2 p3 = __half22float2(u2h(gB3.x)), le3 = __half22float2(u2h(gB3.y));
                float s = le0.y + le1.y + le2.y + le3.y;
                float sq = le0.y * le0.y + le1.y * le1.y + le2.y * le2.y + le3.y * le3.y;
                float lin = finb + le0.x + le1.x + le2.x + le3.x;
#pragma unroll
                for (int c = 0; c < 8; c++) {
                    float e = fmaf(xcB[c], cw[c], cbv[c]);
                    s += e;
                    sq = fmaf(e, e, sq);
                    lin = fmaf(xcB[c], clw[c], lin);
                }
                out[(size_t)rB * 32 + lane] = lin + 0.5f * (s * s - sq);
                float a0 = cb0 + p0.x + p1.x + p2.x + p3.x;
                float a1 = cb1 + p0.y + p1.y + p2.y + p3.y;
#pragma unroll
                for (int c = 0; c < 8; c++) {
                    a0 = fmaf(xcB[c], A0[c], a0);
                    a1 = fmaf(xcB[c], A1[c], a1);
                }
                g_h1h[(size_t)rB * 32 + lane] = __floats2half2_rn(a0, a1);
                sum0 += a0; sq0 = fmaf(a0, a0, sq0);
                sum1 += a1; sq1 = fmaf(a1, a1, sq1);
            }
        }

        __syncthreads();   // before reusing union (phase0 had no smem use; safe anyway)
        u.s1.rs[lane][warp] = sum0; u.s1.rs[lane + 32][warp] = sum1;
        u.s1.rq[lane][warp] = sq0;  u.s1.rq[lane + 32][warp] = sq1;
        __syncthreads();
        int t = tid;
        if (t < 64) {
            float a = 0.f;
#pragma unroll
            for (int w = 0; w < 8; w++) a += u.s1.rs[t][w];
            g_part1[bid * 128 + t] = a;
        } else if (t < 128) {
            float a = 0.f;
#pragma unroll
            for (int w = 0; w < 8; w++) a += u.s1.rq[t - 64][w];
            g_part1[bid * 128 + t] = a;
        }
    }

    // ---- barrier 1 (+ BN1 finalize by last block) ----
    __syncthreads();
    if (tid == 0) {
        __threadfence();
        unsigned tk = atomicAdd(&g_barA[1], 1u);
        s_tgt = (tk / GRIDu + 1u) * GRIDu;
        s_last = (tk % GRIDu == GRIDu - 1u) ? 1 : 0;
    }
    __syncthreads();
    if (s_last) {
        int t = tid;
        int ch = t & 127;
        int half = t >> 7;   // 2 slices of 222 blocks
        float a = 0.f;
        int b0 = half * (GRID / 2);
        for (int b = b0; b < b0 + GRID / 2; b++) a += g_part1[b * 128 + ch];
        u.fin[t] = a;
        __syncthreads();
        if (t < 64) {
            float s = u.fin[t] + u.fin[128 + t];
            float q = u.fin[64 + t] + u.fin[192 + t];
            float mean = s / (float)NROWS;
            float var = q / (float)NROWS - mean * mean;
            float scale = g1[t] * rsqrtf(var + BN_EPS);
            g_bn1[t] = scale;
            g_bn1[64 + t] = beta1[t] - mean * scale;
        }
        __syncthreads();
        if (tid == 0) { __threadfence(); atomicAdd(&g_barR[1], GRIDu); }
    } else if (tid == 0) {
        while (atomicAdd(&g_barR[1], 0u) < s_tgt) __nanosleep(64);
        __threadfence();
    }
    __syncthreads();

    // ===== Phase 2: h2 = relu(bn1(h1)) @ w2^T + b2 (smem-tiled FFMA) =====
    {
        int tr = lane >> 3, tj = lane & 7;
        int j0 = tj * 4;
        for (int i = tid; i < 2048; i += 256) {
            int j = i >> 6, k = i & 63;
            u.s3.wt[k * 36 + j] = w2[i];
        }
        if (tid < 64) { u.s3.sc[tid] = g_bn1[tid]; u.s3.sh[tid] = g_bn1[64 + tid]; }
        float bj[4];
#pragma unroll
        for (int c = 0; c < 4; c++) bj[c] = b2[j0 + c];
        __syncthreads();

        float lsum[4] = {0.f, 0.f, 0.f, 0.f}, lsq[4] = {0.f, 0.f, 0.f, 0.f};
        int rbase = warp * 16 + tr;

        for (int tile = bid; tile < N_TILES; tile += GRID) {
            size_t base = (size_t)tile * TILE_R;
            for (int i = tid; i < TILE_R * 8; i += 256) {
                int r = i >> 3, c4 = (i & 7) * 4;
                uint4 raw = *(const uint4*)&g_h1h[(base + r) * 32 + c4];
                const __half2* hp = (const __half2*)&raw;
                float lo[4], hi[4];
#pragma unroll
                for (int m = 0; m < 4; m++) {
                    float2 f = __half22float2(hp[m]);
                    lo[m] = fmaxf(fmaf(f.x, u.s3.sc[c4 + m], u.s3.sh[c4 + m]), 0.f);
                    hi[m] = fmaxf(fmaf(f.y, u.s3.sc[c4 + m + 32], u.s3.sh[c4 + m + 32]), 0.f);
                }
                *(float4*)&u.s3.a[r * 68 + c4] = make_float4(lo[0], lo[1], lo[2], lo[3]);
                *(float4*)&u.s3.a[r * 68 + 32 + c4] = make_float4(hi[0], hi[1], hi[2], hi[3]);
            }
            __syncthreads();

            float acc[4][4];
#pragma unroll
            for (int i = 0; i < 4; i++)
#pragma unroll
                for (int c = 0; c < 4; c++) acc[i][c] = 0.f;

#pragma unroll 4
            for (int k = 0; k < 64; k += 4) {
                float4 w0 = *(float4*)&u.s3.wt[(k + 0) * 36 + j0];
                float4 w1v = *(float4*)&u.s3.wt[(k + 1) * 36 + j0];
                float4 w2v = *(float4*)&u.s3.wt[(k + 2) * 36 + j0];
                float4 w3 = *(float4*)&u.s3.wt[(k + 3) * 36 + j0];
#pragma unroll
                for (int i = 0; i < 4; i++) {
                    float4 av = *(float4*)&u.s3.a[(rbase + i * 4) * 68 + k];
                    acc[i][0] = fmaf(av.x, w0.x, acc[i][0]);
                    acc[i][1] = fmaf(av.x, w0.y, acc[i][1]);
                    acc[i][2] = fmaf(av.x, w0.z, acc[i][2]);
                    acc[i][3] = fmaf(av.x, w0.w, acc[i][3]);
                    acc[i][0] = fmaf(av.y, w1v.x, acc[i][0]);
                    acc[i][1] = fmaf(av.y, w1v.y, acc[i][1]);
                    acc[i][2] = fmaf(av.y, w1v.z, acc[i][2]);
                    acc[i][3] = fmaf(av.y, w1v.w, acc[i][3]);
                    acc[i][0] = fmaf(av.z, w2v.x, acc[i][0]);
                    acc[i][1] = fmaf(av.z, w2v.y, acc[i][1]);
                    acc[i][2] = fmaf(av.z, w2v.z, acc[i][2]);
                    acc[i][3] = fmaf(av.z, w2v.w, acc[i][3]);
                    acc[i][0] = fmaf(av.w, w3.x, acc[i][0]);
                    acc[i][1] = fmaf(av.w, w3.y, acc[i][1]);
                    acc[i][2] = fmaf(av.w, w3.z, acc[i][2]);
                    acc[i][3] = fmaf(av.w, w3.w, acc[i][3]);
                }
            }

#pragma unroll
            for (int i = 0; i < 4; i++) {
                size_t r = base + rbase + i * 4;
                float v0 = acc[i][0] + bj[0];
                float v1 = acc[i][1] + bj[1];
                float v2 = acc[i][2] + bj[2];
                float v3 = acc[i][3] + bj[3];
                uint2 pk;
                pk.x = h2u(__floats2half2_rn(v0, v1));
                pk.y = h2u(__floats2half2_rn(v2, v3));
                *(uint2*)&g_h2h[r * 32 + j0] = pk;
                lsum[0] += v0; lsq[0] = fmaf(v0, v0, lsq[0]);
                lsum[1] += v1; lsq[1] = fmaf(v1, v1, lsq[1]);
                lsum[2] += v2; lsq[2] = fmaf(v2, v2, lsq[2]);
                lsum[3] += v3; lsq[3] = fmaf(v3, v3, lsq[3]);
            }
            __syncthreads();
        }

#pragma unroll
        for (int c = 0; c < 4; c++) {
            lsum[c] += __shfl_xor_sync(FULL, lsum[c], 8);
            lsum[c] += __shfl_xor_sync(FULL, lsum[c], 16);
            lsq[c] += __shfl_xor_sync(FULL, lsq[c], 8);
            lsq[c] += __shfl_xor_sync(FULL, lsq[c], 16);
        }
        if (tr == 0) {
#pragma unroll
            for (int c = 0; c < 4; c++) {
                u.s3.wsum[warp * 32 + j0 + c] = lsum[c];
                u.s3.wsq[warp * 32 + j0 + c] = lsq[c];
            }
        }
        __syncthreads();
        int t = tid;
        if (t < 32) {
            float s = 0.f;
#pragma unroll
            for (int w = 0; w < 8; w++) s += u.s3.wsum[w * 32 + t];
            g_part2[bid * 64 + t] = s;
        } else if (t < 64) {
            float q = 0.f;
#pragma unroll
            for (int w = 0; w < 8; w++) q += u.s3.wsq[w * 32 + (t - 32)];
            g_part2[bid * 64 + t] = q;
        }
    }

    // ---- barrier 2 (+ BN2 finalize by last block) ----
    __syncthreads();
    if (tid == 0) {
        __threadfence();
        unsigned tk = atomicAdd(&g_barA[2], 1u);
        s_tgt = (tk / GRIDu + 1u) * GRIDu;
        s_last = (tk % GRIDu == GRIDu - 1u) ? 1 : 0;
    }
    __syncthreads();
    if (s_last) {
        int t = tid;
        int ch = t & 63;
        int sl = t >> 6;   // 4 slices of 111 blocks
        float aa = 0.f;
        int b0 = sl * (GRID / 4);
        for (int b = b0; b < b0 + GRID / 4; b++) aa += g_part2[b * 64 + ch];
        u.fin[t] = aa;
        __syncthreads();
        if (t < 32) {
            float s = (u.fin[t] + u.fin[64 + t]) + (u.fin[128 + t] + u.fin[192 + t]);
            float q = (u.fin[32 + t] + u.fin[96 + t]) + (u.fin[160 + t] + u.fin[224 + t]);
            float mean = s / (float)NROWS;
            float var = q / (float)NROWS - mean * mean;
            float scale = g2[t] * rsqrtf(var + BN_EPS);
            g_bn2[t] = scale;
            g_bn2[32 + t] = beta2[t] - mean * scale;
        }
        __syncthreads();
        if (tid == 0) { __threadfence(); atomicAdd(&g_barR[2], GRIDu); }
    } else if (tid == 0) {
        while (atomicAdd(&g_barR[2], 0u) < s_tgt) __nanosleep(64);
        __threadfence();
    }
    __syncthreads();

    // ===== Phase 3: out += relu(bn2(h2)) @ wout^T + bout =====
    {
        int tr = lane >> 3, tj = lane & 7;
        int j0 = tj * 4;
        for (int i = tid; i < 1024; i += 256) {
            int j = i >> 5, k = i & 31;
            u.s5.wt[k * 36 + j] = wout[i];
        }
        if (tid < 32) { u.s5.sc[tid] = g_bn2[tid]; u.s5.sh[tid] = g_bn2[32 + tid]; }
        float bj[4];
#pragma unroll
        for (int c = 0; c < 4; c++) bj[c] = bout[j0 + c];
        __syncthreads();

        int rbase = warp * 16 + tr;

        for (int tile = bid; tile < N_TILES; tile += GRID) {
            size_t base = (size_t)tile * TILE_R;
            for (int i = tid; i < TILE_R * 4; i += 256) {
                int r = i >> 2, c8 = (i & 3) * 8;
                uint4 raw = *(const uint4*)&g_h2h[(base + r) * 32 + c8];
                const __half2* hp = (const __half2*)&raw;
                float f[8];
#pragma unroll
                for (int m = 0; m < 4; m++) {
                    float2 p = __half22float2(hp[m]);
                    f[2 * m] = p.x;
                    f[2 * m + 1] = p.y;
                }
#pragma unroll
                for (int m = 0; m < 8; m++)
                    f[m] = fmaxf(fmaf(f[m], u.s5.sc[c8 + m], u.s5.sh[c8 + m]), 0.f);
                *(float4*)&u.s5.a[r * 36 + c8] = make_float4(f[0], f[1], f[2], f[3]);
                *(float4*)&u.s5.a[r * 36 + c8 + 4] = make_float4(f[4], f[5], f[6], f[7]);
            }
            __syncthreads();

            float acc[4][4];
#pragma unroll
            for (int i = 0; i < 4; i++)
#pragma unroll
                for (int c = 0; c < 4; c++) acc[i][c] = 0.f;

#pragma unroll 4
            for (int k = 0; k < 32; k += 4) {
                float4 w0 = *(float4*)&u.s5.wt[(k + 0) * 36 + j0];
                float4 w1v = *(float4*)&u.s5.wt[(k + 1) * 36 + j0];
                float4 w2v = *(float4*)&u.s5.wt[(k + 2) * 36 + j0];
                float4 w3 = *(float4*)&u.s5.wt[(k + 3) * 36 + j0];
#pragma unroll
                for (int i = 0; i < 4; i++) {
                    float4 av = *(float4*)&u.s5.a[(rbase + i * 4) * 36 + k];
                    acc[i][0] = fmaf(av.x, w0.x, acc[i][0]);
                    acc[i][1] = fmaf(av.x, w0.y, acc[i][1]);
                    acc[i][2] = fmaf(av.x, w0.z, acc[i][2]);
                    acc[i][3] = fmaf(av.x, w0.w, acc[i][3]);
                    acc[i][0] = fmaf(av.y, w1v.x, acc[i][0]);
                    acc[i][1] = fmaf(av.y, w1v.y, acc[i][1]);
                    acc[i][2] = fmaf(av.y, w1v.z, acc[i][2]);
                    acc[i][3] = fmaf(av.y, w1v.w, acc[i][3]);
                    acc[i][0] = fmaf(av.z, w2v.x, acc[i][0]);
                    acc[i][1] = fmaf(av.z, w2v.y, acc[i][1]);
                    acc[i][2] = fmaf(av.z, w2v.z, acc[i][2]);
                    acc[i][3] = fmaf(av.z, w2v.w, acc[i][3]);
                    acc[i][0] = fmaf(av.w, w3.x, acc[i][0]);
                    acc[i][1] = fmaf(av.w, w3.y, acc[i][1]);
                    acc[i][2] = fmaf(av.w, w3.z, acc[i][2]);
                    acc[i][3] = fmaf(av.w, w3.w, acc[i][3]);
                }
            }

#pragma unroll
            for (int i = 0; i < 4; i++) {
                size_t r = base + rbase + i * 4;
                float4 o = *(const float4*)&out[r * 32 + j0];
                o.x += acc[i][0] + bj[0];
                o.y += acc[i][1] + bj[1];
                o.z += acc[i][2] + bj[2];
                o.w += acc[i][3] + bj[3];
                *(float4*)&out[r * 32 + j0] = o;
            }
            __syncthreads();
        }
    }
}

// ---------------------------------------------------------------------------
// Input order (setup_inputs dict insertion): x, emb0, lin0, emb1, lin1,
// emb2, lin2, emb3, lin3, cont_w, cont_b, clin_w, clin_b, fin_bias,
// w1, b1, g1, beta1, w2, b2, g2, beta2, w_out, b_out
// ---------------------------------------------------------------------------
extern "C" void kernel_launch(void* const* d_in, const int* in_sizes, int n_in,
                              void* d_out, int out_size) {
    const float* x      = (const float*)d_in[0];
    const float* emb0   = (const float*)d_in[1];
    const float* lin0   = (const float*)d_in[2];
    const float* emb1   = (const float*)d_in[3];
    const float* lin1   = (const float*)d_in[4];
    const float* emb2   = (const float*)d_in[5];
    const float* lin2   = (const float*)d_in[6];
    const float* emb3   = (const float*)d_in[7];
    const float* lin3   = (const float*)d_in[8];
    const float* cont_w = (const float*)d_in[9];
    const float* cont_b = (const float*)d_in[10];
    const float* clin_w = (const float*)d_in[11];
    const float* clin_b = (const float*)d_in[12];
    const float* fin_b  = (const float*)d_in[13];
    const float* w1     = (const float*)d_in[14];
    const float* b1     = (const float*)d_in[15];
    const float* g1     = (const float*)d_in[16];
    const float* beta1  = (const float*)d_in[17];
    const float* w2     = (const float*)d_in[18];
    const float* b2     = (const float*)d_in[19];
    const float* g2     = (const float*)d_in[20];
    const float* beta2  = (const float*)d_in[21];
    const float* w_out  = (const float*)d_in[22];
    const float* b_out  = (const float*)d_in[23];
    float* out = (float*)d_out;

    kFused<<<GRID, 256>>>(x, emb0, lin0, emb1, lin1, emb2, lin2, emb3, lin3,
                          cont_w, cont_b, clin_w, clin_b, fin_b,
                          w1, b1, g1, beta1, w2, b2, g2, beta2,
                          w_out, b_out, out);
}